// round 3
// baseline (speedup 1.0000x reference)
#include <cuda_runtime.h>
#include <math.h>

#define NMAX 50000
#define HASHSZ (1u<<21)
#define HASHMASK (HASHSZ-1u)
#define WST 257
#define LSTM_SMEM (2*64*WST*4)

// ---------------- scratch ----------------
__device__ float g_X1 [NMAX*64];
__device__ float g_H  [NMAX*64];
__device__ float g_B1 [NMAX*64];
__device__ float g_B2 [NMAX*64];
__device__ float g_RES[NMAX*64];
__device__ float g_dinv0[NMAX];
__device__ float g_dinvP[NMAX];
__device__ float g_score[NMAX];
__device__ float g_kept[NMAX];
__device__ float g_sdeg[NMAX];
__device__ float g_tdeg[NMAX];
__device__ unsigned g_key[NMAX];
__device__ int   g_icnt[NMAX];
__device__ int   g_cc[NMAX];
__device__ int   g_mi[NMAX];
__device__ int   g_pos[NMAX];
__device__ int   g_hist[65536];
__device__ int   g_tie[4096];
__device__ int   g_M, g_tcnt, g_selB, g_before, g_needed;
__device__ unsigned g_T;
__device__ float g_pwnorm;
__device__ unsigned long long g_hk[HASHSZ];
__device__ int   g_hc[HASHSZ];

__device__ __forceinline__ float sigf(float x){ return 1.0f/(1.0f+expf(-x)); }

// ---------------- utility ----------------
__global__ void k_small(){ g_M=0; g_tcnt=0; }
__global__ void k_zero_i(int* p, int n){ int i=blockIdx.x*blockDim.x+threadIdx.x; if(i<n) p[i]=0; }
__global__ void k_zero_f(float* p, int n){ int i=blockIdx.x*blockDim.x+threadIdx.x; if(i<n) p[i]=0.0f; }

__global__ void k_indeg(const int* __restrict__ col, int e){
    int i=blockIdx.x*blockDim.x+threadIdx.x;
    if(i<e) atomicAdd(&g_icnt[col[i]],1);
}
__global__ void k_dinv0k(int n){
    int i=blockIdx.x*blockDim.x+threadIdx.x;
    if(i<n) g_dinv0[i]=rsqrtf((float)g_icnt[i]+2.0f);
}

// ---------------- dense GEMM: out[n x 64] = X[n x K](row-scaled) @ W[K x 64] ----
template<int K>
__global__ void k_gemm(const float* __restrict__ X, const float* __restrict__ W,
                       const float* __restrict__ rs, float* __restrict__ out, int n){
    __shared__ float sW[K*64];
    __shared__ float sX[16*K];
    int tid=threadIdx.x;
    for(int i=tid;i<K*64;i+=256) sW[i]=W[i];
    int r0=blockIdx.x*16;
    for(int i=tid;i<16*K;i+=256){
        int rr=i/K, kk=i%K, row=r0+rr;
        float v=0.0f;
        if(row<n){ v=X[row*K+kk]; if(rs) v*=rs[row]; }
        sX[i]=v;
    }
    __syncthreads();
    int c=tid&63, rg=tid>>6;
    float a0=0,a1=0,a2=0,a3=0;
    #pragma unroll 8
    for(int kk=0;kk<K;kk++){
        float w=sW[kk*64+c];
        a0+=sX[(rg*4+0)*K+kk]*w;
        a1+=sX[(rg*4+1)*K+kk]*w;
        a2+=sX[(rg*4+2)*K+kk]*w;
        a3+=sX[(rg*4+3)*K+kk]*w;
    }
    int row=r0+rg*4;
    if(row+0<n) out[(row+0)*64+c]=a0;
    if(row+1<n) out[(row+1)*64+c]=a1;
    if(row+2<n) out[(row+2)*64+c]=a2;
    if(row+3<n) out[(row+3)*64+c]=a3;
}

// ---------------- GCN pieces ----------------
__global__ void k_selfinit(float* __restrict__ dst, const float* __restrict__ h, int n64){
    int i=blockIdx.x*blockDim.x+threadIdx.x;
    if(i<n64) dst[i]=2.0f*g_dinv0[i>>6]*h[i];
}
__global__ void k_fin(float* __restrict__ dst, const float* __restrict__ acc,
                      const float* __restrict__ b, int n64, int dorelu){
    int i=blockIdx.x*blockDim.x+threadIdx.x;
    if(i<n64){
        int r=i>>6, f=i&63;
        float v=g_dinv0[r]*acc[i]+b[f];
        dst[i]=dorelu?fmaxf(v,0.0f):v;
    }
}
__global__ void k_scat64(float* __restrict__ dst, const float* __restrict__ src,
                         const float* __restrict__ sc, const int* __restrict__ row,
                         const int* __restrict__ col, int e){
    long long t=(long long)blockIdx.x*blockDim.x+threadIdx.x;
    if(t>=(long long)e*16) return;
    int ee=(int)(t>>4), q=((int)t&15)*4;
    int r=row[ee], c=col[ee];
    float4 v=*(const float4*)&src[r*64+q];
    if(sc){ float s=sc[r]; v.x*=s; v.y*=s; v.z*=s; v.w*=s; }
    float* d=&dst[c*64+q];
    atomicAdd(d+0,v.x); atomicAdd(d+1,v.y); atomicAdd(d+2,v.z); atomicAdd(d+3,v.w);
}
__global__ void k_scat1(float* __restrict__ dst, const float* __restrict__ src,
                        const int* __restrict__ row, const int* __restrict__ col, int e){
    int i=blockIdx.x*blockDim.x+threadIdx.x;
    if(i<e) atomicAdd(&dst[col[i]], src[row[i]]);
}

// ---------------- score + radix select (top-k of keys) ----------------
__global__ void k_pwnorm(const float* __restrict__ pw){
    int l=threadIdx.x;
    float v=pw[l]*pw[l]+pw[l+32]*pw[l+32];
    for(int o=16;o;o>>=1) v+=__shfl_down_sync(0xffffffffu,v,o);
    if(l==0) g_pwnorm=sqrtf(v);
}
__global__ void k_score(const float* __restrict__ pw, int n){
    int w=(blockIdx.x*blockDim.x+threadIdx.x)>>5;
    int l=threadIdx.x&31;
    if(w>=n) return;
    float v=g_X1[w*64+l]*pw[l]+g_X1[w*64+l+32]*pw[l+32];
    for(int o=16;o;o>>=1) v+=__shfl_down_sync(0xffffffffu,v,o);
    if(l==0){
        float s=tanhf(v/g_pwnorm);
        g_score[w]=s;
        unsigned b=__float_as_uint(s);
        g_key[w]=(b&0x80000000u)?~b:(b|0x80000000u);
    }
}
__global__ void k_hist1(int n){
    int i=blockIdx.x*blockDim.x+threadIdx.x;
    if(i<n) atomicAdd(&g_hist[g_key[i]>>16],1);
}
__global__ void k_find1(int kk){
    __shared__ int cs[256];
    int t=threadIdx.x, s=0;
    for(int b=0;b<256;b++) s+=g_hist[t*256+b];
    cs[t]=s; __syncthreads();
    if(t==0){
        int acc=0;
        for(int c=255;c>=0;c--){
            if(acc+cs[c]>=kk){
                for(int b=c*256+255;b>=c*256;b--){
                    acc+=g_hist[b];
                    if(acc>=kk){ g_selB=b; g_before=acc-g_hist[b]; return; }
                }
            }
            acc+=cs[c];
        }
        g_selB=0; g_before=0;
    }
}
__global__ void k_hist2(int n){
    int i=blockIdx.x*blockDim.x+threadIdx.x;
    if(i<n){ unsigned u=g_key[i]; if((int)(u>>16)==g_selB) atomicAdd(&g_hist[u&0xFFFFu],1); }
}
__global__ void k_find2(int kk){
    __shared__ int cs[256];
    int t=threadIdx.x, s=0;
    for(int b=0;b<256;b++) s+=g_hist[t*256+b];
    cs[t]=s; __syncthreads();
    if(t==0){
        int rem=kk-g_before, acc=0;
        for(int c=255;c>=0;c--){
            if(acc+cs[c]>=rem){
                for(int b=c*256+255;b>=c*256;b--){
                    acc+=g_hist[b];
                    if(acc>=rem){
                        g_T=((unsigned)g_selB<<16)|(unsigned)b;
                        g_needed=rem-(acc-g_hist[b]);
                        return;
                    }
                }
            }
            acc+=cs[c];
        }
        g_T=0; g_needed=0;
    }
}
__global__ void k_mark(int n){
    int i=blockIdx.x*blockDim.x+threadIdx.x;
    if(i<n){
        unsigned u=g_key[i];
        g_kept[i]=(u>g_T)?1.0f:0.0f;
        if(u==g_T){ int p=atomicAdd(&g_tcnt,1); if(p<4096) g_tie[p]=i; }
    }
}
__global__ void k_tiefix(){
    int need=g_needed, tc=g_tcnt; if(tc>4096) tc=4096;
    for(int s=0;s<need&&s<tc;s++){
        int mb=s;
        for(int j=s+1;j<tc;j++) if(g_tie[j]<g_tie[mb]) mb=j;
        int tmp=g_tie[s]; g_tie[s]=g_tie[mb]; g_tie[mb]=tmp;
        g_kept[g_tie[s]]=1.0f;
    }
}

// ---------------- edge-multiplicity hash → diagonal of M^2 ----------------
__device__ __forceinline__ unsigned hmix(unsigned long long x){
    x^=x>>30; x*=0xbf58476d1ce4e5b9ull;
    x^=x>>27; x*=0x94d049bb133111ebull;
    x^=x>>31;
    return (unsigned)x&HASHMASK;
}
__global__ void k_hash_clear(){
    int i=blockIdx.x*blockDim.x+threadIdx.x;
    if(i<(int)HASHSZ){ g_hk[i]=~0ull; g_hc[i]=0; }
}
__global__ void k_hash_ins(const int* __restrict__ row, const int* __restrict__ col, int e, int n){
    int i=blockIdx.x*blockDim.x+threadIdx.x;
    if(i>=e) return;
    unsigned long long key=(unsigned long long)row[i]*(unsigned)n+(unsigned)col[i];
    unsigned h=hmix(key);
    while(true){
        unsigned long long prev=atomicCAS(&g_hk[h],~0ull,key);
        if(prev==~0ull||prev==key){ atomicAdd(&g_hc[h],1); break; }
        h=(h+1)&HASHMASK;
    }
}
__global__ void k_ccK(const int* __restrict__ row, const int* __restrict__ col, int e, int n){
    int i=blockIdx.x*blockDim.x+threadIdx.x;
    if(i>=e) return;
    unsigned long long key=(unsigned long long)col[i]*(unsigned)n+(unsigned)row[i];
    unsigned h=hmix(key);
    int cnt=0;
    while(true){
        unsigned long long k2=g_hk[h];
        if(k2==key){ cnt=g_hc[h]; break; }
        if(k2==~0ull) break;
        h=(h+1)&HASHMASK;
    }
    if(cnt) atomicAdd(&g_cc[row[i]],cnt);
}
__global__ void k_dinvPk(int n){
    int i=blockIdx.x*blockDim.x+threadIdx.x;
    if(i<n){
        float degP=g_tdeg[i]+2.0f*g_sdeg[i]+2.0f-(float)g_cc[i];
        g_dinvP[i]=(g_kept[i]>0.5f)?rsqrtf(degP):0.0f;
    }
}
// up[c] = relu(dinvP*(t + 2s + (2-cc)*dinvP*h2) + b1) for kept c, else 0 (in-place on g_B2)
__global__ void k_x2up(const float* __restrict__ b1, int n64){
    int i=blockIdx.x*blockDim.x+threadIdx.x;
    if(i<n64){
        int r=i>>6, f=i&63;
        float dp=g_dinvP[r];
        float v=0.0f;
        if(dp!=0.0f){
            float m=dp*g_H[i];
            v=dp*(g_B1[i]+2.0f*g_B2[i]+(2.0f-(float)g_cc[r])*m)+b1[f];
            v=fmaxf(v,0.0f);
        }
        g_B2[i]=v;
    }
}
__global__ void k_mik(const int* __restrict__ mask, int n){
    int i=blockIdx.x*blockDim.x+threadIdx.x;
    if(i<n){
        int p=-1;
        if(mask[i]!=0){ p=atomicAdd(&g_M,1); g_mi[p]=i; }
        g_pos[i]=p;
    }
}
__global__ void k_xin(int n64){
    int i=blockIdx.x*blockDim.x+threadIdx.x;
    if(i<n64){
        int r=i>>6, f=i&63;
        int p=g_pos[r];
        float v=(p>=0)?g_B1[p*64+f]:g_X1[i];
        g_RES[i]=v+g_B2[i];
    }
}
__global__ void k_scat_out(float* __restrict__ out, int n64){
    int i=blockIdx.x*blockDim.x+threadIdx.x;
    if(i<n64){
        int p=i>>6;
        if(p<g_M) out[g_mi[p]*64+(i&63)]=g_B1[i];
    }
}

// ---------------- LSTM: warp handles 4 sequences; weights transposed in smem -----
__global__ __launch_bounds__(512,1) void k_lstm(
    const float* __restrict__ Xin,
    const float* __restrict__ Wih, const float* __restrict__ Whh,
    const float* __restrict__ bih, const float* __restrict__ bhh,
    float* __restrict__ out){
    extern __shared__ float sm[];
    float* sWi=sm;
    float* sWh=sm+64*WST;
    int tid=threadIdx.x;
    for(int i=tid;i<256*64;i+=512){
        int g=i>>6, f=i&63;
        sWi[f*WST+g]=Wih[i];
        sWh[f*WST+g]=Whh[i];
    }
    __syncthreads();
    int wid=tid>>5, lane=tid&31;
    int M=g_M;
    int base=(blockIdx.x*16+wid)*4;
    if(base>=M) return;
    int rid[4];
    #pragma unroll
    for(int nn=0;nn<4;nn++) rid[nn]=(base+nn<M)?g_mi[base+nn]:-1;
    float bs[8];
    #pragma unroll
    for(int j=0;j<8;j++) bs[j]=bih[lane+32*j]+bhh[lane+32*j];
    float hl[4]={0,0,0,0}, hh[4]={0,0,0,0}, cl[4]={0,0,0,0}, ch[4]={0,0,0,0};
    for(int t=0;t<5;t++){
        float xl[4], xh[4];
        #pragma unroll
        for(int nn=0;nn<4;nn++){
            int sr=rid[nn]-4+t;
            bool ok=(rid[nn]>=0)&&(sr>=0);
            xl[nn]=ok?Xin[sr*64+lane]:0.0f;
            xh[nn]=ok?Xin[sr*64+lane+32]:0.0f;
        }
        float acc[4][8];
        #pragma unroll
        for(int nn=0;nn<4;nn++)
            #pragma unroll
            for(int j=0;j<8;j++) acc[nn][j]=bs[j];
        #pragma unroll 4
        for(int f=0;f<64;f++){
            float wi[8], wh[8];
            #pragma unroll
            for(int j=0;j<8;j++){ wi[j]=sWi[f*WST+lane+32*j]; wh[j]=sWh[f*WST+lane+32*j]; }
            #pragma unroll
            for(int nn=0;nn<4;nn++){
                float xv=__shfl_sync(0xffffffffu,(f<32)?xl[nn]:xh[nn],f&31);
                float hv=__shfl_sync(0xffffffffu,(f<32)?hl[nn]:hh[nn],f&31);
                #pragma unroll
                for(int j=0;j<8;j++) acc[nn][j]+=xv*wi[j]+hv*wh[j];
            }
        }
        #pragma unroll
        for(int nn=0;nn<4;nn++){
            float gi=sigf(acc[nn][0]), gf=sigf(acc[nn][2]);
            float gg=tanhf(acc[nn][4]), go=sigf(acc[nn][6]);
            cl[nn]=gf*cl[nn]+gi*gg; hl[nn]=go*tanhf(cl[nn]);
            gi=sigf(acc[nn][1]); gf=sigf(acc[nn][3]);
            gg=tanhf(acc[nn][5]); go=sigf(acc[nn][7]);
            ch[nn]=gf*ch[nn]+gi*gg; hh[nn]=go*tanhf(ch[nn]);
        }
    }
    #pragma unroll
    for(int nn=0;nn<4;nn++){
        if(rid[nn]>=0){
            out[(base+nn)*64+lane]=hl[nn];
            out[(base+nn)*64+lane+32]=hh[nn];
        }
    }
}

// ---------------- host ----------------
extern "C" void kernel_launch(void* const* d_in, const int* in_sizes, int n_in,
                              void* d_out, int out_size){
    const float* x=(const float*)d_in[0];
    const int* row=(const int*)d_in[1];
    const int* mask=(const int*)d_in[2];
    const float* W0=(const float*)d_in[3];  const float* b0=(const float*)d_in[4];
    const float* W1=(const float*)d_in[5];  const float* b1=(const float*)d_in[6];
    const float* pw=(const float*)d_in[7];
    const float* Wu=(const float*)d_in[8];  const float* bu=(const float*)d_in[9];
    const float* l0wih=(const float*)d_in[10]; const float* l0whh=(const float*)d_in[11];
    const float* l0bih=(const float*)d_in[12]; const float* l0bhh=(const float*)d_in[13];
    const float* fwih=(const float*)d_in[14];  const float* fwhh=(const float*)d_in[15];
    const float* fbih=(const float*)d_in[16];  const float* fbhh=(const float*)d_in[17];
    float* out=(float*)d_out;

    int n=in_sizes[0]/32;
    int e=in_sizes[1]/2;
    const int* col=row+e;
    int kk=(n+1)/2;                 // ceil(0.5*n)
    int n64=n*64;
    int GN=(n+255)/256, GN64=(n64+255)/256, GE=(e+255)/256;
    int GS=(int)(((long long)e*16+255)/256);
    int GL=(n+63)/64;               // LSTM blocks (worst case M=n)

    static int smem_set=0;
    if(!smem_set){
        cudaFuncSetAttribute(k_lstm, cudaFuncAttributeMaxDynamicSharedMemorySize, LSTM_SMEM);
        smem_set=1;
    }

    float *dX1,*dH,*dB1,*dB2,*dRES,*dsdeg,*dtdeg;
    int *dicnt,*dcc,*dhist;
    cudaGetSymbolAddress((void**)&dX1,g_X1);
    cudaGetSymbolAddress((void**)&dH,g_H);
    cudaGetSymbolAddress((void**)&dB1,g_B1);
    cudaGetSymbolAddress((void**)&dB2,g_B2);
    cudaGetSymbolAddress((void**)&dRES,g_RES);
    cudaGetSymbolAddress((void**)&dsdeg,g_sdeg);
    cudaGetSymbolAddress((void**)&dtdeg,g_tdeg);
    cudaGetSymbolAddress((void**)&dicnt,g_icnt);
    cudaGetSymbolAddress((void**)&dcc,g_cc);
    cudaGetSymbolAddress((void**)&dhist,g_hist);
    float *dkept; cudaGetSymbolAddress((void**)&dkept,g_kept);
    float *dscore; cudaGetSymbolAddress((void**)&dscore,g_score);
    float *ddinvP; cudaGetSymbolAddress((void**)&ddinvP,g_dinvP);
    float *ddinv0; cudaGetSymbolAddress((void**)&ddinv0,g_dinv0);

    // init
    k_small<<<1,1>>>();
    k_zero_i<<<GN,256>>>(dicnt,n);
    k_zero_i<<<GN,256>>>(dcc,n);

    // conv0: x1 = relu(GCN(x))
    k_indeg<<<GE,256>>>(col,e);
    k_dinv0k<<<GN,256>>>(n);
    k_gemm<32><<<(n+15)/16,256>>>(x,W0,(const float*)0,dH,n);
    k_selfinit<<<GN64,256>>>(dB1,dH,n64);
    k_scat64<<<GS,256>>>(dB1,dH,ddinv0,row,col,e);
    k_fin<<<GN64,256>>>(dX1,dB1,b0,n64,1);

    // topk select
    k_pwnorm<<<1,32>>>(pw);
    k_score<<<(n*32+255)/256,256>>>(pw,n);
    k_zero_i<<<256,256>>>(dhist,65536);
    k_hist1<<<GN,256>>>(n);
    k_find1<<<1,256>>>(kk);
    k_zero_i<<<256,256>>>(dhist,65536);
    k_hist2<<<GN,256>>>(n);
    k_find2<<<1,256>>>(kk);
    k_mark<<<GN,256>>>(n);
    k_tiefix<<<1,1>>>();

    // diagonal of M^2 via hash
    k_hash_clear<<<(int)(HASHSZ/256),256>>>();
    k_hash_ins<<<GE,256>>>(row,col,e,n);
    k_ccK<<<GE,256>>>(row,col,e,n);

    // pooled degrees: deg = 2 + t_deg + 2*s_deg - cc
    k_zero_f<<<GN,256>>>(dsdeg,n);
    k_scat1<<<GE,256>>>(dsdeg,dkept,row,col,e);
    k_zero_f<<<GN,256>>>(dtdeg,n);
    k_scat1<<<GE,256>>>(dtdeg,dsdeg,row,col,e);
    k_dinvPk<<<GN,256>>>(n);

    // conv1 on pooled graph (orig index space)
    k_gemm<64><<<(n+15)/16,256>>>(dX1,W1,dscore,dH,n);       // h2 = (x1*score)@W1
    k_zero_f<<<GN64,256>>>(dB2,n64);
    k_scat64<<<GS,256>>>(dB2,dH,ddinvP,row,col,e);           // s = M^T m
    k_zero_f<<<GN64,256>>>(dB1,n64);
    k_scat64<<<GS,256>>>(dB1,dB2,(const float*)0,row,col,e); // t = M^T s
    k_x2up<<<GN64,256>>>(b1,n64);                            // UP -> g_B2

    // masked indices + LSTM0 on x1 windows
    k_mik<<<GN,256>>>(mask,n);
    k_lstm<<<GL,512,LSTM_SMEM>>>(dX1,l0wih,l0whh,l0bih,l0bhh,dB1); // h0 -> g_B1
    k_xin<<<GN64,256>>>(n64);                                // RES = (res)+up

    // final GCN -> d_out
    k_gemm<64><<<(n+15)/16,256>>>(dRES,Wu,(const float*)0,dH,n);
    k_selfinit<<<GN64,256>>>(dB1,dH,n64);
    k_scat64<<<GS,256>>>(dB1,dH,ddinv0,row,col,e);
    k_fin<<<GN64,256>>>(out,dB1,bu,n64,0);

    // final LSTM on xo windows, scatter back
    k_lstm<<<GL,512,LSTM_SMEM>>>(out,fwih,fwhh,fbih,fbhh,dB1);
    k_scat_out<<<GN64,256>>>(out,n64);
}

// round 4
// speedup vs baseline: 1.3958x; 1.3958x over previous
#include <cuda_runtime.h>
#include <math.h>

#define NMAX 50000
#define HASHSZ (1u<<21)
#define HASHMASK (HASHSZ-1u)
#define LSTM_SMEM (2*64*256*4)

// ---------------- scratch ----------------
__device__ float g_X1 [NMAX*64];
__device__ float g_H  [NMAX*64];
__device__ float g_B1 [NMAX*64];
__device__ float g_B2 [NMAX*64];
__device__ float g_RES[NMAX*64];
__device__ float g_dinv0[NMAX];
__device__ float g_dinvP[NMAX];
__device__ float g_score[NMAX];
__device__ float g_kept[NMAX];
__device__ float g_sdeg[NMAX];
__device__ float g_tdeg[NMAX];
__device__ unsigned g_key[NMAX];
__device__ int   g_icnt[NMAX];
__device__ int   g_cc[NMAX];
__device__ int   g_mi[NMAX];
__device__ int   g_pos[NMAX];
__device__ int   g_hist[65536];
__device__ int   g_tie[4096];
__device__ int   g_M, g_tcnt, g_selB, g_before, g_needed;
__device__ unsigned g_T;
__device__ float g_pwnorm;
__device__ unsigned long long g_hk[HASHSZ];
__device__ int   g_hc[HASHSZ];

__device__ __forceinline__ float sigf(float x){ return 1.0f/(1.0f+expf(-x)); }

#define FMA2(A,B,C) asm("fma.rn.f32x2 %0,%1,%2,%0;":"+l"(A):"l"(B),"l"(C))
#define PACK2(D,LO,HI) asm("mov.b64 %0,{%1,%2};":"=l"(D):"f"(LO),"f"(HI))
#define BCAST2(D,V) asm("mov.b64 %0,{%1,%1};":"=l"(D):"f"(V))
#define UNPACK2(LO,HI,S) asm("mov.b64 {%0,%1},%2;":"=f"(LO),"=f"(HI):"l"(S))

// ---------------- fused init ----------------
__global__ void k_init(int n){
    int i=blockIdx.x*blockDim.x+threadIdx.x;
    if(i<(int)HASHSZ){ g_hk[i]=~0ull; g_hc[i]=0; }
    if(i<n){ g_icnt[i]=0; g_cc[i]=0; g_sdeg[i]=0.0f; g_tdeg[i]=0.0f; }
    if(i==0){ g_M=0; g_tcnt=0; }
}
__global__ void k_zero_i(int* p, int n){ int i=blockIdx.x*blockDim.x+threadIdx.x; if(i<n) p[i]=0; }
__global__ void k_zero2v(float4* a, float4* b, int n4){
    int i=blockIdx.x*blockDim.x+threadIdx.x;
    float4 z=make_float4(0,0,0,0);
    if(i<n4){ a[i]=z; b[i]=z; }
}
__global__ void k_indeg(const int* __restrict__ col, int e){
    int i=blockIdx.x*blockDim.x+threadIdx.x;
    if(i<e) atomicAdd(&g_icnt[col[i]],1);
}
__global__ void k_dinv0k(int n){
    int i=blockIdx.x*blockDim.x+threadIdx.x;
    if(i<n) g_dinv0[i]=rsqrtf((float)g_icnt[i]+2.0f);
}

// ---------------- dense GEMM: out[n x 64] = X[n x K](row-scaled) @ W[K x 64] ----
template<int K>
__global__ void k_gemm(const float* __restrict__ X, const float* __restrict__ W,
                       const float* __restrict__ rs, float* __restrict__ out, int n){
    __shared__ float sW[K*64];
    __shared__ float sX[16*K];
    int tid=threadIdx.x;
    for(int i=tid;i<K*64;i+=256) sW[i]=W[i];
    int r0=blockIdx.x*16;
    for(int i=tid;i<16*K;i+=256){
        int rr=i/K, kk=i%K, row=r0+rr;
        float v=0.0f;
        if(row<n){ v=X[row*K+kk]; if(rs) v*=rs[row]; }
        sX[i]=v;
    }
    __syncthreads();
    int c=tid&63, rg=tid>>6;
    float a0=0,a1=0,a2=0,a3=0;
    #pragma unroll 8
    for(int kk=0;kk<K;kk++){
        float w=sW[kk*64+c];
        a0+=sX[(rg*4+0)*K+kk]*w;
        a1+=sX[(rg*4+1)*K+kk]*w;
        a2+=sX[(rg*4+2)*K+kk]*w;
        a3+=sX[(rg*4+3)*K+kk]*w;
    }
    int row=r0+rg*4;
    if(row+0<n) out[(row+0)*64+c]=a0;
    if(row+1<n) out[(row+1)*64+c]=a1;
    if(row+2<n) out[(row+2)*64+c]=a2;
    if(row+3<n) out[(row+3)*64+c]=a3;
}

// ---------------- GCN pieces (vectorized) ----------------
__global__ void k_selfinit4(float4* __restrict__ dst, const float4* __restrict__ h, int n16){
    int i=blockIdx.x*blockDim.x+threadIdx.x;
    if(i<n16){
        float s=2.0f*g_dinv0[i>>4];
        float4 v=h[i];
        v.x*=s; v.y*=s; v.z*=s; v.w*=s;
        dst[i]=v;
    }
}
__global__ void k_fin4(float4* __restrict__ dst, const float4* __restrict__ acc,
                       const float* __restrict__ b, int n16, int dorelu){
    int i=blockIdx.x*blockDim.x+threadIdx.x;
    if(i<n16){
        float s=g_dinv0[i>>4];
        float4 bv=*(const float4*)&b[(i&15)*4];
        float4 v=acc[i];
        v.x=s*v.x+bv.x; v.y=s*v.y+bv.y; v.z=s*v.z+bv.z; v.w=s*v.w+bv.w;
        if(dorelu){ v.x=fmaxf(v.x,0.f); v.y=fmaxf(v.y,0.f); v.z=fmaxf(v.z,0.f); v.w=fmaxf(v.w,0.f); }
        dst[i]=v;
    }
}
__global__ void k_scat64(float* __restrict__ dst, const float* __restrict__ src,
                         const float* __restrict__ sc, const int* __restrict__ row,
                         const int* __restrict__ col, int e){
    int t=blockIdx.x*blockDim.x+threadIdx.x;
    if(t>=e*16) return;
    int ee=t>>4, q=(t&15)*4;
    int r=row[ee], c=col[ee];
    float s=1.0f;
    if(sc){ s=sc[r]; if(s==0.0f) return; }
    float4 v=*(const float4*)&src[r*64+q];
    v.x*=s; v.y*=s; v.z*=s; v.w*=s;
    asm volatile("red.global.add.v4.f32 [%0], {%1,%2,%3,%4};"
        ::"l"(&dst[c*64+q]),"f"(v.x),"f"(v.y),"f"(v.z),"f"(v.w):"memory");
}
__global__ void k_scat1(float* __restrict__ dst, const float* __restrict__ src,
                        const int* __restrict__ row, const int* __restrict__ col, int e){
    int i=blockIdx.x*blockDim.x+threadIdx.x;
    if(i<e){
        float v=src[row[i]];
        if(v!=0.0f)
            asm volatile("red.global.add.f32 [%0], %1;"::"l"(&dst[col[i]]),"f"(v):"memory");
    }
}

// ---------------- score + radix select ----------------
__global__ void k_pwnorm(const float* __restrict__ pw){
    int l=threadIdx.x;
    float v=pw[l]*pw[l]+pw[l+32]*pw[l+32];
    for(int o=16;o;o>>=1) v+=__shfl_down_sync(0xffffffffu,v,o);
    if(l==0) g_pwnorm=sqrtf(v);
}
__global__ void k_score(const float* __restrict__ pw, int n){
    int w=(blockIdx.x*blockDim.x+threadIdx.x)>>5;
    int l=threadIdx.x&31;
    if(w>=n) return;
    float v=g_X1[w*64+l]*pw[l]+g_X1[w*64+l+32]*pw[l+32];
    for(int o=16;o;o>>=1) v+=__shfl_down_sync(0xffffffffu,v,o);
    if(l==0){
        float s=tanhf(v/g_pwnorm);
        g_score[w]=s;
        unsigned b=__float_as_uint(s);
        g_key[w]=(b&0x80000000u)?~b:(b|0x80000000u);
    }
}
__global__ void k_hist1(int n){
    int i=blockIdx.x*blockDim.x+threadIdx.x;
    if(i<n) atomicAdd(&g_hist[g_key[i]>>16],1);
}
__global__ void k_find1(int kk){
    __shared__ int cs[256];
    int t=threadIdx.x, s=0;
    for(int b=0;b<256;b++) s+=g_hist[t*256+b];
    cs[t]=s; __syncthreads();
    if(t==0){
        int acc=0;
        for(int c=255;c>=0;c--){
            if(acc+cs[c]>=kk){
                for(int b=c*256+255;b>=c*256;b--){
                    acc+=g_hist[b];
                    if(acc>=kk){ g_selB=b; g_before=acc-g_hist[b]; return; }
                }
            }
            acc+=cs[c];
        }
        g_selB=0; g_before=0;
    }
}
__global__ void k_hist2(int n){
    int i=blockIdx.x*blockDim.x+threadIdx.x;
    if(i<n){ unsigned u=g_key[i]; if((int)(u>>16)==g_selB) atomicAdd(&g_hist[u&0xFFFFu],1); }
}
__global__ void k_find2(int kk){
    __shared__ int cs[256];
    int t=threadIdx.x, s=0;
    for(int b=0;b<256;b++) s+=g_hist[t*256+b];
    cs[t]=s; __syncthreads();
    if(t==0){
        int rem=kk-g_before, acc=0;
        for(int c=255;c>=0;c--){
            if(acc+cs[c]>=rem){
                for(int b=c*256+255;b>=c*256;b--){
                    acc+=g_hist[b];
                    if(acc>=rem){
                        g_T=((unsigned)g_selB<<16)|(unsigned)b;
                        g_needed=rem-(acc-g_hist[b]);
                        return;
                    }
                }
            }
            acc+=cs[c];
        }
        g_T=0; g_needed=0;
    }
}
__global__ void k_mark(int n){
    int i=blockIdx.x*blockDim.x+threadIdx.x;
    if(i<n){
        unsigned u=g_key[i];
        g_kept[i]=(u>g_T)?1.0f:0.0f;
        if(u==g_T){ int p=atomicAdd(&g_tcnt,1); if(p<4096) g_tie[p]=i; }
    }
}
__global__ void k_tiefix(){
    int need=g_needed, tc=g_tcnt; if(tc>4096) tc=4096;
    for(int s=0;s<need&&s<tc;s++){
        int mb=s;
        for(int j=s+1;j<tc;j++) if(g_tie[j]<g_tie[mb]) mb=j;
        int tmp=g_tie[s]; g_tie[s]=g_tie[mb]; g_tie[mb]=tmp;
        g_kept[g_tie[s]]=1.0f;
    }
}

// ---------------- edge-multiplicity hash → diagonal of M^2 ----------------
__device__ __forceinline__ unsigned hmix(unsigned long long x){
    x^=x>>30; x*=0xbf58476d1ce4e5b9ull;
    x^=x>>27; x*=0x94d049bb133111ebull;
    x^=x>>31;
    return (unsigned)x&HASHMASK;
}
__global__ void k_hash_ins(const int* __restrict__ row, const int* __restrict__ col, int e, int n){
    int i=blockIdx.x*blockDim.x+threadIdx.x;
    if(i>=e) return;
    unsigned long long key=(unsigned long long)row[i]*(unsigned)n+(unsigned)col[i];
    unsigned h=hmix(key);
    while(true){
        unsigned long long prev=atomicCAS(&g_hk[h],~0ull,key);
        if(prev==~0ull||prev==key){ atomicAdd(&g_hc[h],1); break; }
        h=(h+1)&HASHMASK;
    }
}
__global__ void k_ccK(const int* __restrict__ row, const int* __restrict__ col, int e, int n){
    int i=blockIdx.x*blockDim.x+threadIdx.x;
    if(i>=e) return;
    unsigned long long key=(unsigned long long)col[i]*(unsigned)n+(unsigned)row[i];
    unsigned h=hmix(key);
    int cnt=0;
    while(true){
        unsigned long long k2=g_hk[h];
        if(k2==key){ cnt=g_hc[h]; break; }
        if(k2==~0ull) break;
        h=(h+1)&HASHMASK;
    }
    if(cnt) atomicAdd(&g_cc[row[i]],cnt);
}
__global__ void k_dinvPk(int n){
    int i=blockIdx.x*blockDim.x+threadIdx.x;
    if(i<n){
        float degP=g_tdeg[i]+2.0f*g_sdeg[i]+2.0f-(float)g_cc[i];
        g_dinvP[i]=(g_kept[i]>0.5f)?rsqrtf(degP):0.0f;
    }
}
__global__ void k_x2up4(const float* __restrict__ b1, int n16){
    int i=blockIdx.x*blockDim.x+threadIdx.x;
    if(i<n16){
        int r=i>>4;
        float dp=g_dinvP[r];
        float4 v=make_float4(0,0,0,0);
        if(dp!=0.0f){
            float cf=(2.0f-(float)g_cc[r])*dp;
            float4 t=((const float4*)g_B1)[i];
            float4 s=((const float4*)g_B2)[i];
            float4 h=((const float4*)g_H)[i];
            float4 bv=*(const float4*)&b1[(i&15)*4];
            v.x=fmaxf(dp*(t.x+2.0f*s.x+cf*h.x)+bv.x,0.f);
            v.y=fmaxf(dp*(t.y+2.0f*s.y+cf*h.y)+bv.y,0.f);
            v.z=fmaxf(dp*(t.z+2.0f*s.z+cf*h.z)+bv.z,0.f);
            v.w=fmaxf(dp*(t.w+2.0f*s.w+cf*h.w)+bv.w,0.f);
        }
        ((float4*)g_B2)[i]=v;
    }
}
__global__ void k_mik(const int* __restrict__ mask, int n){
    int i=blockIdx.x*blockDim.x+threadIdx.x;
    if(i<n){
        int p=-1;
        if(mask[i]!=0){ p=atomicAdd(&g_M,1); g_mi[p]=i; }
        g_pos[i]=p;
    }
}
__global__ void k_xin4(int n16){
    int i=blockIdx.x*blockDim.x+threadIdx.x;
    if(i<n16){
        int r=i>>4, fq=i&15;
        int p=g_pos[r];
        float4 v=(p>=0)?((const float4*)g_B1)[p*16+fq]:((const float4*)g_X1)[i];
        float4 u=((const float4*)g_B2)[i];
        v.x+=u.x; v.y+=u.y; v.z+=u.z; v.w+=u.w;
        ((float4*)g_RES)[i]=v;
    }
}
__global__ void k_scat_out4(float* __restrict__ out, int n16){
    int i=blockIdx.x*blockDim.x+threadIdx.x;
    if(i<n16){
        int p=i>>4;
        if(p<g_M) *(float4*)&out[g_mi[p]*64+(i&15)*4]=((const float4*)g_B1)[i];
    }
}

// ---------------- LSTM: warp = 4 seqs; packed f32x2 FMA; paired weight layout ----
__global__ __launch_bounds__(512,1) void k_lstm(
    const float* __restrict__ Xin,
    const float* __restrict__ Wih, const float* __restrict__ Whh,
    const float* __restrict__ bih, const float* __restrict__ bhh,
    float* __restrict__ out){
    extern __shared__ float sm[];
    float* sWi=sm;
    float* sWh=sm+64*256;
    int tid=threadIdx.x;
    int M=g_M;
    if(blockIdx.x*64>=M) return;
    // paired layout: sW[f*256 + k*64 + laneg*2 + half] = W[(laneg + 64k + 32*half)*64 + f]
    for(int i=tid*4;i<256*64;i+=512*4){
        int g=i>>6, f0=i&63;
        int j=g>>5, lg=g&31, kp=j>>1, half=j&1;
        int dbase=kp*64+lg*2+half;
        float4 wi=*(const float4*)&Wih[i];
        float4 wh=*(const float4*)&Whh[i];
        sWi[dbase+(f0+0)*256]=wi.x; sWi[dbase+(f0+1)*256]=wi.y;
        sWi[dbase+(f0+2)*256]=wi.z; sWi[dbase+(f0+3)*256]=wi.w;
        sWh[dbase+(f0+0)*256]=wh.x; sWh[dbase+(f0+1)*256]=wh.y;
        sWh[dbase+(f0+2)*256]=wh.z; sWh[dbase+(f0+3)*256]=wh.w;
    }
    __syncthreads();
    int wid=tid>>5, lane=tid&31;
    int base=(blockIdx.x*16+wid)*4;
    if(base>=M) return;
    int rid[4];
    #pragma unroll
    for(int nn=0;nn<4;nn++) rid[nn]=(base+nn<M)?g_mi[base+nn]:-1;
    unsigned long long bs[4];
    #pragma unroll
    for(int kp=0;kp<4;kp++){
        float blo=bih[lane+64*kp]+bhh[lane+64*kp];
        float bhi=bih[lane+64*kp+32]+bhh[lane+64*kp+32];
        PACK2(bs[kp],blo,bhi);
    }
    float hl[4]={0,0,0,0}, hh[4]={0,0,0,0}, cl[4]={0,0,0,0}, ch[4]={0,0,0,0};
    for(int t=0;t<5;t++){
        float xl[4], xh[4];
        #pragma unroll
        for(int nn=0;nn<4;nn++){
            int sr=rid[nn]-4+t;
            bool ok=(rid[nn]>=0)&&(sr>=0);
            xl[nn]=ok?Xin[sr*64+lane]:0.0f;
            xh[nn]=ok?Xin[sr*64+lane+32]:0.0f;
        }
        unsigned long long acc[4][4];
        #pragma unroll
        for(int nn=0;nn<4;nn++)
            #pragma unroll
            for(int kp=0;kp<4;kp++) acc[nn][kp]=bs[kp];

        #define LSTM_F(F,XS,HS) { \
            const unsigned long long* wiP=(const unsigned long long*)&sWi[(F)*256]+lane; \
            const unsigned long long* whP=(const unsigned long long*)&sWh[(F)*256]+lane; \
            unsigned long long wi0=wiP[0],wi1=wiP[32],wi2=wiP[64],wi3=wiP[96]; \
            unsigned long long wh0=whP[0],wh1=whP[32],wh2=whP[64],wh3=whP[96]; \
            _Pragma("unroll") \
            for(int nn=0;nn<4;nn++){ \
                float xv=__shfl_sync(0xffffffffu,XS[nn],(F)&31); \
                float hv=__shfl_sync(0xffffffffu,HS[nn],(F)&31); \
                unsigned long long xp,hp; \
                BCAST2(xp,xv); BCAST2(hp,hv); \
                FMA2(acc[nn][0],xp,wi0); FMA2(acc[nn][0],hp,wh0); \
                FMA2(acc[nn][1],xp,wi1); FMA2(acc[nn][1],hp,wh1); \
                FMA2(acc[nn][2],xp,wi2); FMA2(acc[nn][2],hp,wh2); \
                FMA2(acc[nn][3],xp,wi3); FMA2(acc[nn][3],hp,wh3); \
            } }

        #pragma unroll 8
        for(int f=0;f<32;f++) LSTM_F(f,xl,hl)
        #pragma unroll 8
        for(int f=32;f<64;f++) LSTM_F(f,xh,hh)
        #undef LSTM_F

        #pragma unroll
        for(int nn=0;nn<4;nn++){
            float il,ih,fl,fh,gl,gh,ol,oh;
            UNPACK2(il,ih,acc[nn][0]);
            UNPACK2(fl,fh,acc[nn][1]);
            UNPACK2(gl,gh,acc[nn][2]);
            UNPACK2(ol,oh,acc[nn][3]);
            cl[nn]=sigf(fl)*cl[nn]+sigf(il)*tanhf(gl); hl[nn]=sigf(ol)*tanhf(cl[nn]);
            ch[nn]=sigf(fh)*ch[nn]+sigf(ih)*tanhf(gh); hh[nn]=sigf(oh)*tanhf(ch[nn]);
        }
    }
    #pragma unroll
    for(int nn=0;nn<4;nn++){
        if(rid[nn]>=0){
            out[(base+nn)*64+lane]=hl[nn];
            out[(base+nn)*64+lane+32]=hh[nn];
        }
    }
}

// ---------------- host ----------------
extern "C" void kernel_launch(void* const* d_in, const int* in_sizes, int n_in,
                              void* d_out, int out_size){
    const float* x=(const float*)d_in[0];
    const int* row=(const int*)d_in[1];
    const int* mask=(const int*)d_in[2];
    const float* W0=(const float*)d_in[3];  const float* b0=(const float*)d_in[4];
    const float* W1=(const float*)d_in[5];  const float* b1=(const float*)d_in[6];
    const float* pw=(const float*)d_in[7];
    const float* Wu=(const float*)d_in[8];  const float* bu=(const float*)d_in[9];
    const float* l0wih=(const float*)d_in[10]; const float* l0whh=(const float*)d_in[11];
    const float* l0bih=(const float*)d_in[12]; const float* l0bhh=(const float*)d_in[13];
    const float* fwih=(const float*)d_in[14];  const float* fwhh=(const float*)d_in[15];
    const float* fbih=(const float*)d_in[16];  const float* fbhh=(const float*)d_in[17];
    float* out=(float*)d_out;

    int n=in_sizes[0]/32;
    int e=in_sizes[1]/2;
    const int* col=row+e;
    int kk=(n+1)/2;
    int n64=n*64, n16=n*16, n4=n64/4;
    int GN=(n+255)/256, GN16=(n16+255)/256, GE=(e+255)/256;
    int GS=(e*16+255)/256;
    int GL=(n+63)/64;

    static int smem_set=0;
    if(!smem_set){
        cudaFuncSetAttribute(k_lstm, cudaFuncAttributeMaxDynamicSharedMemorySize, LSTM_SMEM);
        smem_set=1;
    }

    float *dX1,*dH,*dB1,*dB2,*dRES,*dsdeg,*dtdeg;
    int *dhist;
    cudaGetSymbolAddress((void**)&dX1,g_X1);
    cudaGetSymbolAddress((void**)&dH,g_H);
    cudaGetSymbolAddress((void**)&dB1,g_B1);
    cudaGetSymbolAddress((void**)&dB2,g_B2);
    cudaGetSymbolAddress((void**)&dRES,g_RES);
    cudaGetSymbolAddress((void**)&dsdeg,g_sdeg);
    cudaGetSymbolAddress((void**)&dtdeg,g_tdeg);
    cudaGetSymbolAddress((void**)&dhist,g_hist);
    float *dkept; cudaGetSymbolAddress((void**)&dkept,g_kept);
    float *dscore; cudaGetSymbolAddress((void**)&dscore,g_score);
    float *ddinvP; cudaGetSymbolAddress((void**)&ddinvP,g_dinvP);
    float *ddinv0; cudaGetSymbolAddress((void**)&ddinv0,g_dinv0);

    // fused init: hash table + per-node counters + small counters
    k_init<<<(int)(HASHSZ/256),256>>>(n);

    // conv0: x1 = relu(GCN(x))
    k_indeg<<<GE,256>>>(col,e);
    k_dinv0k<<<GN,256>>>(n);
    k_gemm<32><<<(n+15)/16,256>>>(x,W0,(const float*)0,dH,n);
    k_selfinit4<<<GN16,256>>>((float4*)dB1,(const float4*)dH,n16);
    k_scat64<<<GS,256>>>(dB1,dH,ddinv0,row,col,e);
    k_fin4<<<GN16,256>>>((float4*)dX1,(const float4*)dB1,b0,n16,1);

    // topk select
    k_pwnorm<<<1,32>>>(pw);
    k_score<<<(n*32+255)/256,256>>>(pw,n);
    k_zero_i<<<256,256>>>(dhist,65536);
    k_hist1<<<GN,256>>>(n);
    k_find1<<<1,256>>>(kk);
    k_zero_i<<<256,256>>>(dhist,65536);
    k_hist2<<<GN,256>>>(n);
    k_find2<<<1,256>>>(kk);
    k_mark<<<GN,256>>>(n);
    k_tiefix<<<1,1>>>();

    // diagonal of M^2 via hash
    k_hash_ins<<<GE,256>>>(row,col,e,n);
    k_ccK<<<GE,256>>>(row,col,e,n);

    // pooled degrees: deg = 2 + t_deg + 2*s_deg - cc  (sdeg/tdeg zeroed in k_init)
    k_scat1<<<GE,256>>>(dsdeg,dkept,row,col,e);
    k_scat1<<<GE,256>>>(dtdeg,dsdeg,row,col,e);
    k_dinvPk<<<GN,256>>>(n);

    // conv1 on pooled graph (orig index space)
    k_gemm<64><<<(n+15)/16,256>>>(dX1,W1,dscore,dH,n);       // h2 = (x1*score)@W1
    k_zero2v<<<(n4+255)/256,256>>>((float4*)dB1,(float4*)dB2,n4);
    k_scat64<<<GS,256>>>(dB2,dH,ddinvP,row,col,e);           // s = M^T m (skip zero rows)
    k_scat64<<<GS,256>>>(dB1,dB2,(const float*)0,row,col,e); // t = M^T s
    k_x2up4<<<GN16,256>>>(b1,n16);                           // UP -> g_B2

    // masked indices + LSTM0 on x1 windows
    k_mik<<<GN,256>>>(mask,n);
    k_lstm<<<GL,512,LSTM_SMEM>>>(dX1,l0wih,l0whh,l0bih,l0bhh,dB1); // h0 -> g_B1
    k_xin4<<<GN16,256>>>(n16);                               // RES = res + up

    // final GCN -> d_out
    k_gemm<64><<<(n+15)/16,256>>>(dRES,Wu,(const float*)0,dH,n);
    k_selfinit4<<<GN16,256>>>((float4*)dB1,(const float4*)dH,n16);
    k_scat64<<<GS,256>>>(dB1,dH,ddinv0,row,col,e);
    k_fin4<<<GN16,256>>>((float4*)out,(const float4*)dB1,bu,n16,0);

    // final LSTM on xo windows, scatter back
    k_lstm<<<GL,512,LSTM_SMEM>>>(out,fwih,fwhh,fbih,fbhh,dB1);
    k_scat_out4<<<GN16,256>>>(out,n16);
}

// round 5
// speedup vs baseline: 1.5446x; 1.1066x over previous
#include <cuda_runtime.h>
#include <math.h>

#define NMAX 50000
#define HASHSZ (1u<<21)
#define HASHMASK (HASHSZ-1u)
#define WSMEM (64*256*4)
#define PGRID 444

// ---------------- scratch ----------------
__device__ float g_X1 [NMAX*64];
__device__ float g_H  [NMAX*64];
__device__ float g_B1 [NMAX*64];
__device__ float g_B2 [NMAX*64];
__device__ float g_RES[NMAX*64];
__device__ unsigned long long g_GX[NMAX*128];
__device__ float g_dinv0[NMAX];
__device__ float g_dinvP[NMAX];
__device__ float g_score[NMAX];
__device__ float g_kept[NMAX];
__device__ float g_sdeg[NMAX];
__device__ float g_tdeg[NMAX];
__device__ unsigned g_key[NMAX];
__device__ int   g_icnt[NMAX];
__device__ int   g_cc[NMAX];
__device__ int   g_mi[NMAX];
__device__ int   g_pos[NMAX];
__device__ int   g_hist[65536];
__device__ int   g_tie[4096];
__device__ int   g_M, g_tcnt, g_selB, g_before, g_needed;
__device__ unsigned g_T;
__device__ float g_pwnorm;
__device__ unsigned long long g_hk[HASHSZ];
__device__ int   g_hc[HASHSZ];

__device__ __forceinline__ float sigf(float x){ return 1.0f/(1.0f+expf(-x)); }

#define FMA2(A,B,C) asm("fma.rn.f32x2 %0,%1,%2,%0;":"+l"(A):"l"(B),"l"(C))
#define PACK2(D,LO,HI) asm("mov.b64 %0,{%1,%2};":"=l"(D):"f"(LO),"f"(HI))
#define BCAST2(D,V) asm("mov.b64 %0,{%1,%1};":"=l"(D):"f"(V))
#define UNPACK2(LO,HI,S) asm("mov.b64 {%0,%1},%2;":"=f"(LO),"=f"(HI):"l"(S))

// ---------------- fused init ----------------
__global__ void k_init(int n){
    int i=blockIdx.x*blockDim.x+threadIdx.x;
    if(i<(int)HASHSZ){ g_hk[i]=~0ull; g_hc[i]=0; }
    if(i<n){ g_icnt[i]=0; g_cc[i]=0; g_sdeg[i]=0.0f; g_tdeg[i]=0.0f; }
    if(i==0){ g_M=0; g_tcnt=0; }
}
__global__ void k_zero_i(int* p, int n){ int i=blockIdx.x*blockDim.x+threadIdx.x; if(i<n) p[i]=0; }
__global__ void k_zero2v(float4* a, float4* b, int n4){
    int i=blockIdx.x*blockDim.x+threadIdx.x;
    float4 z=make_float4(0,0,0,0);
    if(i<n4){ a[i]=z; b[i]=z; }
}
__global__ void k_indeg(const int* __restrict__ col, int e){
    int i=blockIdx.x*blockDim.x+threadIdx.x;
    if(i<e) atomicAdd(&g_icnt[col[i]],1);
}
__global__ void k_dinv0k(int n){
    int i=blockIdx.x*blockDim.x+threadIdx.x;
    if(i<n) g_dinv0[i]=rsqrtf((float)g_icnt[i]+2.0f);
}

// ------- dense GEMM: out[n x 64] = X[n x K](row-scaled) @ W[K x 64]; optional fused
//         self-term write: selfdst = 2*dinv0[row]*out ----------------------------
template<int K>
__global__ void k_gemm(const float* __restrict__ X, const float* __restrict__ W,
                       const float* __restrict__ rs, float* __restrict__ out,
                       float* __restrict__ selfdst, int n){
    __shared__ float sW[K*64];
    __shared__ float sX[16*K];
    int tid=threadIdx.x;
    for(int i=tid;i<K*64;i+=256) sW[i]=W[i];
    int r0=blockIdx.x*16;
    for(int i=tid;i<16*K;i+=256){
        int rr=i/K, kk=i%K, row=r0+rr;
        float v=0.0f;
        if(row<n){ v=X[row*K+kk]; if(rs) v*=rs[row]; }
        sX[i]=v;
    }
    __syncthreads();
    int c=tid&63, rg=tid>>6;
    float a0=0,a1=0,a2=0,a3=0;
    #pragma unroll 8
    for(int kk=0;kk<K;kk++){
        float w=sW[kk*64+c];
        a0+=sX[(rg*4+0)*K+kk]*w;
        a1+=sX[(rg*4+1)*K+kk]*w;
        a2+=sX[(rg*4+2)*K+kk]*w;
        a3+=sX[(rg*4+3)*K+kk]*w;
    }
    int row=r0+rg*4;
    #pragma unroll
    for(int rr=0;rr<4;rr++){
        float a=(rr==0)?a0:(rr==1)?a1:(rr==2)?a2:a3;
        if(row+rr<n){
            out[(row+rr)*64+c]=a;
            if(selfdst) selfdst[(row+rr)*64+c]=2.0f*g_dinv0[row+rr]*a;
        }
    }
}

// ---------------- GCN pieces ----------------
__global__ void k_fin4(float4* __restrict__ dst, const float4* __restrict__ acc,
                       const float* __restrict__ b, int n16, int dorelu){
    int i=blockIdx.x*blockDim.x+threadIdx.x;
    if(i<n16){
        float s=g_dinv0[i>>4];
        float4 bv=*(const float4*)&b[(i&15)*4];
        float4 v=acc[i];
        v.x=s*v.x+bv.x; v.y=s*v.y+bv.y; v.z=s*v.z+bv.z; v.w=s*v.w+bv.w;
        if(dorelu){ v.x=fmaxf(v.x,0.f); v.y=fmaxf(v.y,0.f); v.z=fmaxf(v.z,0.f); v.w=fmaxf(v.w,0.f); }
        dst[i]=v;
    }
}
// fused conv0-finalize + topk score: warp per row
__global__ void k_fin_score(const float* __restrict__ acc, const float* __restrict__ b0,
                            const float* __restrict__ pw, int n){
    int r=(blockIdx.x*blockDim.x+threadIdx.x)>>5;
    int l=threadIdx.x&31;
    if(r>=n) return;
    float d=g_dinv0[r];
    float vlo=fmaxf(d*acc[r*64+l]+b0[l],0.0f);
    float vhi=fmaxf(d*acc[r*64+l+32]+b0[l+32],0.0f);
    g_X1[r*64+l]=vlo; g_X1[r*64+l+32]=vhi;
    float s=vlo*pw[l]+vhi*pw[l+32];
    for(int o=16;o;o>>=1) s+=__shfl_down_sync(0xffffffffu,s,o);
    if(l==0){
        float sc=tanhf(s/g_pwnorm);
        g_score[r]=sc;
        unsigned bb=__float_as_uint(sc);
        g_key[r]=(bb&0x80000000u)?~bb:(bb|0x80000000u);
    }
}
__global__ void k_scat64(float* __restrict__ dst, const float* __restrict__ src,
                         const float* __restrict__ sc, const int* __restrict__ row,
                         const int* __restrict__ col, int e){
    int t=blockIdx.x*blockDim.x+threadIdx.x;
    if(t>=e*16) return;
    int ee=t>>4, q=(t&15)*4;
    int r=row[ee], c=col[ee];
    float s=1.0f;
    if(sc){ s=sc[r]; if(s==0.0f) return; }
    float4 v=*(const float4*)&src[r*64+q];
    v.x*=s; v.y*=s; v.z*=s; v.w*=s;
    asm volatile("red.global.add.v4.f32 [%0], {%1,%2,%3,%4};"
        ::"l"(&dst[c*64+q]),"f"(v.x),"f"(v.y),"f"(v.z),"f"(v.w):"memory");
}
__global__ void k_scat1(float* __restrict__ dst, const float* __restrict__ src,
                        const int* __restrict__ row, const int* __restrict__ col, int e){
    int i=blockIdx.x*blockDim.x+threadIdx.x;
    if(i<e){
        float v=src[row[i]];
        if(v!=0.0f)
            asm volatile("red.global.add.f32 [%0], %1;"::"l"(&dst[col[i]]),"f"(v):"memory");
    }
}

// ---------------- radix select ----------------
__global__ void k_pwnorm(const float* __restrict__ pw){
    int l=threadIdx.x;
    float v=pw[l]*pw[l]+pw[l+32]*pw[l+32];
    for(int o=16;o;o>>=1) v+=__shfl_down_sync(0xffffffffu,v,o);
    if(l==0) g_pwnorm=sqrtf(v);
}
__global__ void k_hist1(int n){
    int i=blockIdx.x*blockDim.x+threadIdx.x;
    if(i<n) atomicAdd(&g_hist[g_key[i]>>16],1);
}
__global__ void k_find1(int kk){
    __shared__ int cs[256];
    int t=threadIdx.x, s=0;
    for(int b=0;b<256;b++) s+=g_hist[t*256+b];
    cs[t]=s; __syncthreads();
    if(t==0){
        int acc=0;
        for(int c=255;c>=0;c--){
            if(acc+cs[c]>=kk){
                for(int b=c*256+255;b>=c*256;b--){
                    acc+=g_hist[b];
                    if(acc>=kk){ g_selB=b; g_before=acc-g_hist[b]; return; }
                }
            }
            acc+=cs[c];
        }
        g_selB=0; g_before=0;
    }
}
__global__ void k_hist2(int n){
    int i=blockIdx.x*blockDim.x+threadIdx.x;
    if(i<n){ unsigned u=g_key[i]; if((int)(u>>16)==g_selB) atomicAdd(&g_hist[u&0xFFFFu],1); }
}
__global__ void k_find2(int kk){
    __shared__ int cs[256];
    int t=threadIdx.x, s=0;
    for(int b=0;b<256;b++) s+=g_hist[t*256+b];
    cs[t]=s; __syncthreads();
    if(t==0){
        int rem=kk-g_before, acc=0;
        for(int c=255;c>=0;c--){
            if(acc+cs[c]>=rem){
                for(int b=c*256+255;b>=c*256;b--){
                    acc+=g_hist[b];
                    if(acc>=rem){
                        g_T=((unsigned)g_selB<<16)|(unsigned)b;
                        g_needed=rem-(acc-g_hist[b]);
                        return;
                    }
                }
            }
            acc+=cs[c];
        }
        g_T=0; g_needed=0;
    }
}
__global__ void k_mark(int n){
    int i=blockIdx.x*blockDim.x+threadIdx.x;
    if(i<n){
        unsigned u=g_key[i];
        g_kept[i]=(u>g_T)?1.0f:0.0f;
        if(u==g_T){ int p=atomicAdd(&g_tcnt,1); if(p<4096) g_tie[p]=i; }
    }
}
__global__ void k_tiefix(){
    int need=g_needed, tc=g_tcnt; if(tc>4096) tc=4096;
    for(int s=0;s<need&&s<tc;s++){
        int mb=s;
        for(int j=s+1;j<tc;j++) if(g_tie[j]<g_tie[mb]) mb=j;
        int tmp=g_tie[s]; g_tie[s]=g_tie[mb]; g_tie[mb]=tmp;
        g_kept[g_tie[s]]=1.0f;
    }
}

// ---------------- edge-multiplicity hash → diagonal of M^2 ----------------
__device__ __forceinline__ unsigned hmix(unsigned long long x){
    x^=x>>30; x*=0xbf58476d1ce4e5b9ull;
    x^=x>>27; x*=0x94d049bb133111ebull;
    x^=x>>31;
    return (unsigned)x&HASHMASK;
}
__global__ void k_hash_ins(const int* __restrict__ row, const int* __restrict__ col, int e, int n){
    int i=blockIdx.x*blockDim.x+threadIdx.x;
    if(i>=e) return;
    unsigned long long key=(unsigned long long)row[i]*(unsigned)n+(unsigned)col[i];
    unsigned h=hmix(key);
    while(true){
        unsigned long long prev=atomicCAS(&g_hk[h],~0ull,key);
        if(prev==~0ull||prev==key){ atomicAdd(&g_hc[h],1); break; }
        h=(h+1)&HASHMASK;
    }
}
__global__ void k_ccK(const int* __restrict__ row, const int* __restrict__ col, int e, int n){
    int i=blockIdx.x*blockDim.x+threadIdx.x;
    if(i>=e) return;
    unsigned long long key=(unsigned long long)col[i]*(unsigned)n+(unsigned)row[i];
    unsigned h=hmix(key);
    int cnt=0;
    while(true){
        unsigned long long k2=g_hk[h];
        if(k2==key){ cnt=g_hc[h]; break; }
        if(k2==~0ull) break;
        h=(h+1)&HASHMASK;
    }
    if(cnt) atomicAdd(&g_cc[row[i]],cnt);
}
__global__ void k_dinvPk(int n){
    int i=blockIdx.x*blockDim.x+threadIdx.x;
    if(i<n){
        float degP=g_tdeg[i]+2.0f*g_sdeg[i]+2.0f-(float)g_cc[i];
        g_dinvP[i]=(g_kept[i]>0.5f)?rsqrtf(degP):0.0f;
    }
}
__global__ void k_x2up4(const float* __restrict__ b1, int n16){
    int i=blockIdx.x*blockDim.x+threadIdx.x;
    if(i<n16){
        int r=i>>4;
        float dp=g_dinvP[r];
        float4 v=make_float4(0,0,0,0);
        if(dp!=0.0f){
            float cf=(2.0f-(float)g_cc[r])*dp;
            float4 t=((const float4*)g_B1)[i];
            float4 s=((const float4*)g_B2)[i];
            float4 h=((const float4*)g_H)[i];
            float4 bv=*(const float4*)&b1[(i&15)*4];
            v.x=fmaxf(dp*(t.x+2.0f*s.x+cf*h.x)+bv.x,0.f);
            v.y=fmaxf(dp*(t.y+2.0f*s.y+cf*h.y)+bv.y,0.f);
            v.z=fmaxf(dp*(t.z+2.0f*s.z+cf*h.z)+bv.z,0.f);
            v.w=fmaxf(dp*(t.w+2.0f*s.w+cf*h.w)+bv.w,0.f);
        }
        ((float4*)g_B2)[i]=v;
    }
}
__global__ void k_mik(const int* __restrict__ mask, int n){
    int i=blockIdx.x*blockDim.x+threadIdx.x;
    if(i<n){
        int p=-1;
        if(mask[i]!=0){ p=atomicAdd(&g_M,1); g_mi[p]=i; }
        g_pos[i]=p;
    }
}
__global__ void k_xin4(int n16){
    int i=blockIdx.x*blockDim.x+threadIdx.x;
    if(i<n16){
        int r=i>>4, fq=i&15;
        int p=g_pos[r];
        float4 v=(p>=0)?((const float4*)g_B1)[p*16+fq]:((const float4*)g_X1)[i];
        float4 u=((const float4*)g_B2)[i];
        v.x+=u.x; v.y+=u.y; v.z+=u.z; v.w+=u.w;
        ((float4*)g_RES)[i]=v;
    }
}
__global__ void k_scat_out4(float* __restrict__ out, int n16){
    int i=blockIdx.x*blockDim.x+threadIdx.x;
    if(i<n16){
        int p=i>>4;
        if(p<g_M) *(float4*)&out[g_mi[p]*64+(i&15)*4]=((const float4*)g_B1)[i];
    }
}

// ------- shared paired-weight smem loader: sW[kp*64+lg*2+half + f*256] = W[(lg+64kp+32half)*64+f]
__device__ __forceinline__ void load_paired(float* sW, const float* __restrict__ W, int tid){
    for(int i=tid*4;i<256*64;i+=256*4){
        int g=i>>6, f0=i&63;
        int j=g>>5, lg=g&31, kp=j>>1, half=j&1;
        int dbase=kp*64+lg*2+half;
        float4 w=*(const float4*)&W[i];
        sW[dbase+(f0+0)*256]=w.x; sW[dbase+(f0+1)*256]=w.y;
        sW[dbase+(f0+2)*256]=w.z; sW[dbase+(f0+3)*256]=w.w;
    }
}

// ------- Gx precompute: Gx[r][kp*32+lane] (u64) = paired gates of x@Wih^T + b  -----
__global__ __launch_bounds__(256) void k_gx(const float* __restrict__ Xsrc,
    const float* __restrict__ Wih, const float* __restrict__ bih,
    const float* __restrict__ bhh, int n){
    extern __shared__ float sWi[];
    int tid=threadIdx.x;
    load_paired(sWi,Wih,tid);
    __syncthreads();
    int wid=tid>>5, lane=tid&31;
    unsigned long long bs[4];
    #pragma unroll
    for(int kp=0;kp<4;kp++){
        float blo=bih[lane+64*kp]+bhh[lane+64*kp];
        float bhi=bih[lane+64*kp+32]+bhh[lane+64*kp+32];
        PACK2(bs[kp],blo,bhi);
    }
    unsigned long long* G=g_GX;
    for(int r0=(blockIdx.x*8+wid)*2; r0<n; r0+=gridDim.x*16){
        int r1=r0+1; bool has1=r1<n;
        float xl0=Xsrc[r0*64+lane], xh0=Xsrc[r0*64+lane+32];
        float xl1=has1?Xsrc[r1*64+lane]:0.0f, xh1=has1?Xsrc[r1*64+lane+32]:0.0f;
        unsigned long long a0[4],a1[4];
        #pragma unroll
        for(int kp=0;kp<4;kp++){ a0[kp]=bs[kp]; a1[kp]=bs[kp]; }
        #define GX_F(F,X0,X1S) { \
            const unsigned long long* wp=(const unsigned long long*)&sWi[(F)*256]+lane; \
            unsigned long long w0=wp[0],w1=wp[32],w2=wp[64],w3=wp[96]; \
            float xv0=__shfl_sync(0xffffffffu,X0,(F)&31); \
            float xv1=__shfl_sync(0xffffffffu,X1S,(F)&31); \
            unsigned long long p0,p1; BCAST2(p0,xv0); BCAST2(p1,xv1); \
            FMA2(a0[0],p0,w0); FMA2(a0[1],p0,w1); FMA2(a0[2],p0,w2); FMA2(a0[3],p0,w3); \
            FMA2(a1[0],p1,w0); FMA2(a1[1],p1,w1); FMA2(a1[2],p1,w2); FMA2(a1[3],p1,w3); }
        #pragma unroll 8
        for(int f=0;f<32;f++) GX_F(f,xl0,xl1)
        #pragma unroll 8
        for(int f=32;f<64;f++) GX_F(f,xh0,xh1)
        #undef GX_F
        #pragma unroll
        for(int kp=0;kp<4;kp++){
            G[r0*128+kp*32+lane]=a0[kp];
            if(has1) G[r1*128+kp*32+lane]=a1[kp];
        }
    }
}

// ------- LSTM recurrence (h-part only; x-part from g_GX; t=0 skips matmul) -------
__global__ __launch_bounds__(256) void k_lstm(
    const float* __restrict__ Whh, const float* __restrict__ bih,
    const float* __restrict__ bhh, float* __restrict__ out){
    extern __shared__ float sWh[];
    int tid=threadIdx.x;
    load_paired(sWh,Whh,tid);
    __syncthreads();
    int wid=tid>>5, lane=tid&31;
    int M=g_M;
    unsigned long long bs[4];
    #pragma unroll
    for(int kp=0;kp<4;kp++){
        float blo=bih[lane+64*kp]+bhh[lane+64*kp];
        float bhi=bih[lane+64*kp+32]+bhh[lane+64*kp+32];
        PACK2(bs[kp],blo,bhi);
    }
    const unsigned long long* G=g_GX;
    for(int base=(blockIdx.x*8+wid)*4; base<M; base+=gridDim.x*32){
        int rid[4];
        #pragma unroll
        for(int nn=0;nn<4;nn++) rid[nn]=(base+nn<M)?g_mi[base+nn]:-1;
        float hl[4]={0,0,0,0}, hh[4]={0,0,0,0}, cl[4]={0,0,0,0}, ch[4]={0,0,0,0};
        for(int t=0;t<5;t++){
            unsigned long long acc[4][4];
            #pragma unroll
            for(int nn=0;nn<4;nn++){
                int sr=rid[nn]-4+t;
                bool ok=(rid[nn]>=0)&&(sr>=0);
                const unsigned long long* gp=G+(ok?sr:0)*128+lane;
                #pragma unroll
                for(int kp=0;kp<4;kp++) acc[nn][kp]=ok?gp[kp*32]:bs[kp];
            }
            if(t>0){
                #define LSTM_F(F,HS) { \
                    const unsigned long long* whP=(const unsigned long long*)&sWh[(F)*256]+lane; \
                    unsigned long long w0=whP[0],w1=whP[32],w2=whP[64],w3=whP[96]; \
                    _Pragma("unroll") \
                    for(int nn=0;nn<4;nn++){ \
                        float hv=__shfl_sync(0xffffffffu,HS[nn],(F)&31); \
                        unsigned long long hp; BCAST2(hp,hv); \
                        FMA2(acc[nn][0],hp,w0); FMA2(acc[nn][1],hp,w1); \
                        FMA2(acc[nn][2],hp,w2); FMA2(acc[nn][3],hp,w3); \
                    } }
                #pragma unroll 8
                for(int f=0;f<32;f++) LSTM_F(f,hl)
                #pragma unroll 8
                for(int f=32;f<64;f++) LSTM_F(f,hh)
                #undef LSTM_F
            }
            #pragma unroll
            for(int nn=0;nn<4;nn++){
                float il,ih,fl,fh,gl,gh,ol,oh;
                UNPACK2(il,ih,acc[nn][0]);
                UNPACK2(fl,fh,acc[nn][1]);
                UNPACK2(gl,gh,acc[nn][2]);
                UNPACK2(ol,oh,acc[nn][3]);
                cl[nn]=sigf(fl)*cl[nn]+sigf(il)*tanhf(gl); hl[nn]=sigf(ol)*tanhf(cl[nn]);
                ch[nn]=sigf(fh)*ch[nn]+sigf(ih)*tanhf(gh); hh[nn]=sigf(oh)*tanhf(ch[nn]);
            }
        }
        #pragma unroll
        for(int nn=0;nn<4;nn++){
            if(rid[nn]>=0){
                out[(base+nn)*64+lane]=hl[nn];
                out[(base+nn)*64+lane+32]=hh[nn];
            }
        }
    }
}

// ---------------- host ----------------
extern "C" void kernel_launch(void* const* d_in, const int* in_sizes, int n_in,
                              void* d_out, int out_size){
    const float* x=(const float*)d_in[0];
    const int* row=(const int*)d_in[1];
    const int* mask=(const int*)d_in[2];
    const float* W0=(const float*)d_in[3];  const float* b0=(const float*)d_in[4];
    const float* W1=(const float*)d_in[5];  const float* b1=(const float*)d_in[6];
    const float* pw=(const float*)d_in[7];
    const float* Wu=(const float*)d_in[8];  const float* bu=(const float*)d_in[9];
    const float* l0wih=(const float*)d_in[10]; const float* l0whh=(const float*)d_in[11];
    const float* l0bih=(const float*)d_in[12]; const float* l0bhh=(const float*)d_in[13];
    const float* fwih=(const float*)d_in[14];  const float* fwhh=(const float*)d_in[15];
    const float* fbih=(const float*)d_in[16];  const float* fbhh=(const float*)d_in[17];
    float* out=(float*)d_out;

    int n=in_sizes[0]/32;
    int e=in_sizes[1]/2;
    const int* col=row+e;
    int kk=(n+1)/2;
    int n64=n*64, n16=n*16, n4=n64/4;
    int GN=(n+255)/256, GN16=(n16+255)/256, GE=(e+255)/256;
    int GS=(e*16+255)/256;

    static int smem_set=0;
    if(!smem_set){
        cudaFuncSetAttribute(k_lstm, cudaFuncAttributeMaxDynamicSharedMemorySize, WSMEM);
        cudaFuncSetAttribute(k_gx,   cudaFuncAttributeMaxDynamicSharedMemorySize, WSMEM);
        smem_set=1;
    }

    float *dX1,*dH,*dB1,*dB2,*dRES,*dsdeg,*dtdeg;
    int *dhist;
    cudaGetSymbolAddress((void**)&dX1,g_X1);
    cudaGetSymbolAddress((void**)&dH,g_H);
    cudaGetSymbolAddress((void**)&dB1,g_B1);
    cudaGetSymbolAddress((void**)&dB2,g_B2);
    cudaGetSymbolAddress((void**)&dRES,g_RES);
    cudaGetSymbolAddress((void**)&dsdeg,g_sdeg);
    cudaGetSymbolAddress((void**)&dtdeg,g_tdeg);
    cudaGetSymbolAddress((void**)&dhist,g_hist);
    float *dkept; cudaGetSymbolAddress((void**)&dkept,g_kept);
    float *dscore; cudaGetSymbolAddress((void**)&dscore,g_score);
    float *ddinvP; cudaGetSymbolAddress((void**)&ddinvP,g_dinvP);
    float *ddinv0; cudaGetSymbolAddress((void**)&ddinv0,g_dinv0);

    // fused init
    k_init<<<(int)(HASHSZ/256),256>>>(n);

    // conv0: x1 = relu(GCN(x)) fused with topk score
    k_indeg<<<GE,256>>>(col,e);
    k_dinv0k<<<GN,256>>>(n);
    k_gemm<32><<<(n+15)/16,256>>>(x,W0,(const float*)0,dH,dB1,n);  // H + self-term in B1
    k_scat64<<<GS,256>>>(dB1,dH,ddinv0,row,col,e);
    k_pwnorm<<<1,32>>>(pw);
    k_fin_score<<<(n*32+255)/256,256>>>(dB1,b0,pw,n);              // X1 + score + key

    // topk select
    k_zero_i<<<256,256>>>(dhist,65536);
    k_hist1<<<GN,256>>>(n);
    k_find1<<<1,256>>>(kk);
    k_zero_i<<<256,256>>>(dhist,65536);
    k_hist2<<<GN,256>>>(n);
    k_find2<<<1,256>>>(kk);
    k_mark<<<GN,256>>>(n);
    k_tiefix<<<1,1>>>();

    // diagonal of M^2 via hash
    k_hash_ins<<<GE,256>>>(row,col,e,n);
    k_ccK<<<GE,256>>>(row,col,e,n);

    // pooled degrees
    k_scat1<<<GE,256>>>(dsdeg,dkept,row,col,e);
    k_scat1<<<GE,256>>>(dtdeg,dsdeg,row,col,e);
    k_dinvPk<<<GN,256>>>(n);

    // conv1 on pooled graph
    k_gemm<64><<<(n+15)/16,256>>>(dX1,W1,dscore,dH,(float*)0,n);   // h2
    k_zero2v<<<(n4+255)/256,256>>>((float4*)dB1,(float4*)dB2,n4);
    k_scat64<<<GS,256>>>(dB2,dH,ddinvP,row,col,e);                 // s
    k_scat64<<<GS,256>>>(dB1,dB2,(const float*)0,row,col,e);       // t
    k_x2up4<<<GN16,256>>>(b1,n16);                                 // UP -> B2

    // masked indices + LSTM0
    k_mik<<<GN,256>>>(mask,n);
    k_gx<<<PGRID,256,WSMEM>>>(dX1,l0wih,l0bih,l0bhh,n);
    k_lstm<<<PGRID,256,WSMEM>>>(l0whh,l0bih,l0bhh,dB1);            // h0 -> B1
    k_xin4<<<GN16,256>>>(n16);                                     // RES

    // final GCN -> out
    k_gemm<64><<<(n+15)/16,256>>>(dRES,Wu,(const float*)0,dH,dB1,n); // H + self-term
    k_scat64<<<GS,256>>>(dB1,dH,ddinv0,row,col,e);
    k_fin4<<<GN16,256>>>((float4*)out,(const float4*)dB1,bu,n16,0);

    // final LSTM
    k_gx<<<PGRID,256,WSMEM>>>(out,fwih,fbih,fbhh,n);
    k_lstm<<<PGRID,256,WSMEM>>>(fwhh,fbih,fbhh,dB1);
    k_scat_out4<<<GN16,256>>>(out,n16);
}

// round 6
// speedup vs baseline: 1.5580x; 1.0086x over previous
#include <cuda_runtime.h>
#include <math.h>

#define NMAX 50000
#define HASHSZ (1u<<21)
#define HASHMASK (HASHSZ-1u)
#define WSMEM (64*256*4)
#define PGRID 444

// ---------------- scratch ----------------
__device__ float g_X1 [NMAX*64];
__device__ float g_H  [NMAX*64];
__device__ float g_B1 [NMAX*64];
__device__ float g_B2 [NMAX*64];
__device__ float g_RES[NMAX*64];
__device__ float g_S  [NMAX*64];
__device__ float g_Tb [NMAX*64];
__device__ unsigned long long g_GX[NMAX*128];
__device__ float g_dinv0[NMAX];
__device__ float g_dinvP[NMAX];
__device__ float g_score[NMAX];
__device__ float g_kept[NMAX];
__device__ float g_sdeg[NMAX];
__device__ float g_tdeg[NMAX];
__device__ unsigned g_key[NMAX];
__device__ int   g_icnt[NMAX];
__device__ int   g_cc[NMAX];
__device__ int   g_mi[NMAX];
__device__ int   g_pos[NMAX];
__device__ int   g_hist[65536];
__device__ int   g_hist2[65536];
__device__ int   g_tie[4096];
__device__ int   g_M, g_tcnt, g_selB, g_before, g_needed;
__device__ unsigned g_T;
__device__ float g_pwnorm;
__device__ unsigned long long g_hk[HASHSZ];
__device__ int   g_hc[HASHSZ];

__device__ __forceinline__ float sigf(float x){ return 1.0f/(1.0f+expf(-x)); }

#define FMA2(A,B,C) asm("fma.rn.f32x2 %0,%1,%2,%0;":"+l"(A):"l"(B),"l"(C))
#define PACK2(D,LO,HI) asm("mov.b64 %0,{%1,%2};":"=l"(D):"f"(LO),"f"(HI))
#define BCAST2(D,V) asm("mov.b64 %0,{%1,%1};":"=l"(D):"f"(V))
#define UNPACK2(LO,HI,S) asm("mov.b64 {%0,%1},%2;":"=f"(LO),"=f"(HI):"l"(S))

// ------- fused init: hash + counters + hists + conv1 accumulators + pwnorm -------
__global__ void k_init(const float* __restrict__ pw, int n, int n16){
    int i=blockIdx.x*blockDim.x+threadIdx.x;
    if(i<(int)HASHSZ){ g_hk[i]=~0ull; g_hc[i]=0; }
    if(i<n){ g_icnt[i]=0; g_cc[i]=0; g_sdeg[i]=0.0f; g_tdeg[i]=0.0f; }
    if(i<65536){ g_hist[i]=0; g_hist2[i]=0; }
    if(i<n16){
        float4 z=make_float4(0,0,0,0);
        ((float4*)g_S)[i]=z; ((float4*)g_Tb)[i]=z;
    }
    if(i==0){ g_M=0; g_tcnt=0; }
    if(blockIdx.x==0&&threadIdx.x<32){
        int l=threadIdx.x;
        float v=pw[l]*pw[l]+pw[l+32]*pw[l+32];
        for(int o=16;o;o>>=1) v+=__shfl_down_sync(0xffffffffu,v,o);
        if(l==0) g_pwnorm=sqrtf(v);
    }
}

// ------- edge pass: in-degree + hash insert --------------------------------------
__device__ __forceinline__ unsigned hmix(unsigned long long x){
    x^=x>>30; x*=0xbf58476d1ce4e5b9ull;
    x^=x>>27; x*=0x94d049bb133111ebull;
    x^=x>>31;
    return (unsigned)x&HASHMASK;
}
__global__ void k_edge0(const int* __restrict__ row, const int* __restrict__ col, int e, int n){
    int i=blockIdx.x*blockDim.x+threadIdx.x;
    if(i>=e) return;
    atomicAdd(&g_icnt[col[i]],1);
    unsigned long long key=(unsigned long long)row[i]*(unsigned)n+(unsigned)col[i];
    unsigned h=hmix(key);
    while(true){
        unsigned long long prev=atomicCAS(&g_hk[h],~0ull,key);
        if(prev==~0ull||prev==key){ atomicAdd(&g_hc[h],1); break; }
        h=(h+1)&HASHMASK;
    }
}

// ------- dense GEMM + optional fused self-term (with optional dinv0 computation) -
template<int K>
__global__ void k_gemm(const float* __restrict__ X, const float* __restrict__ W,
                       const float* __restrict__ rs, float* __restrict__ out,
                       float* __restrict__ selfdst, const int* __restrict__ ic, int n){
    __shared__ float sW[K*64];
    __shared__ float sX[16*K];
    int tid=threadIdx.x;
    for(int i=tid;i<K*64;i+=256) sW[i]=W[i];
    int r0=blockIdx.x*16;
    for(int i=tid;i<16*K;i+=256){
        int rr=i/K, kk=i%K, row=r0+rr;
        float v=0.0f;
        if(row<n){ v=X[row*K+kk]; if(rs) v*=rs[row]; }
        sX[i]=v;
    }
    __syncthreads();
    int c=tid&63, rg=tid>>6;
    float a0=0,a1=0,a2=0,a3=0;
    #pragma unroll 8
    for(int kk=0;kk<K;kk++){
        float w=sW[kk*64+c];
        a0+=sX[(rg*4+0)*K+kk]*w;
        a1+=sX[(rg*4+1)*K+kk]*w;
        a2+=sX[(rg*4+2)*K+kk]*w;
        a3+=sX[(rg*4+3)*K+kk]*w;
    }
    int row=r0+rg*4;
    #pragma unroll
    for(int rr=0;rr<4;rr++){
        float a=(rr==0)?a0:(rr==1)?a1:(rr==2)?a2:a3;
        if(row+rr<n){
            out[(row+rr)*64+c]=a;
            if(selfdst){
                float d;
                if(ic){
                    d=rsqrtf((float)ic[row+rr]+2.0f);
                    if(c==0) g_dinv0[row+rr]=d;
                }else d=g_dinv0[row+rr];
                selfdst[(row+rr)*64+c]=2.0f*d*a;
            }
        }
    }
}

// ---------------- GCN pieces ----------------
__global__ void k_fin4(float4* __restrict__ dst, const float4* __restrict__ acc,
                       const float* __restrict__ b, int n16, int dorelu){
    int i=blockIdx.x*blockDim.x+threadIdx.x;
    if(i<n16){
        float s=g_dinv0[i>>4];
        float4 bv=*(const float4*)&b[(i&15)*4];
        float4 v=acc[i];
        v.x=s*v.x+bv.x; v.y=s*v.y+bv.y; v.z=s*v.z+bv.z; v.w=s*v.w+bv.w;
        if(dorelu){ v.x=fmaxf(v.x,0.f); v.y=fmaxf(v.y,0.f); v.z=fmaxf(v.z,0.f); v.w=fmaxf(v.w,0.f); }
        dst[i]=v;
    }
}
// fused conv0-finalize + topk score + coarse histogram
__global__ void k_fin_score(const float* __restrict__ acc, const float* __restrict__ b0,
                            const float* __restrict__ pw, int n){
    int r=(blockIdx.x*blockDim.x+threadIdx.x)>>5;
    int l=threadIdx.x&31;
    if(r>=n) return;
    float d=g_dinv0[r];
    float vlo=fmaxf(d*acc[r*64+l]+b0[l],0.0f);
    float vhi=fmaxf(d*acc[r*64+l+32]+b0[l+32],0.0f);
    g_X1[r*64+l]=vlo; g_X1[r*64+l+32]=vhi;
    float s=vlo*pw[l]+vhi*pw[l+32];
    for(int o=16;o;o>>=1) s+=__shfl_down_sync(0xffffffffu,s,o);
    if(l==0){
        float sc=tanhf(s/g_pwnorm);
        g_score[r]=sc;
        unsigned bb=__float_as_uint(sc);
        unsigned key=(bb&0x80000000u)?~bb:(bb|0x80000000u);
        g_key[r]=key;
        atomicAdd(&g_hist[key>>16],1);
    }
}
// 4 threads per edge, 4 quads each
__global__ void k_scat64(float* __restrict__ dst, const float* __restrict__ src,
                         const float* __restrict__ sc, const int* __restrict__ row,
                         const int* __restrict__ col, int e){
    int t=blockIdx.x*blockDim.x+threadIdx.x;
    if(t>=e*4) return;
    int ee=t>>2, q0=(t&3)*4;
    int r=row[ee], c=col[ee];
    float s=1.0f;
    if(sc){ s=sc[r]; if(s==0.0f) return; }
    const float4* sp=(const float4*)&src[r*64]+q0;
    float* d=&dst[c*64]+q0*4;
    float4 v0=sp[0],v1=sp[1],v2=sp[2],v3=sp[3];
    v0.x*=s;v0.y*=s;v0.z*=s;v0.w*=s;
    v1.x*=s;v1.y*=s;v1.z*=s;v1.w*=s;
    v2.x*=s;v2.y*=s;v2.z*=s;v2.w*=s;
    v3.x*=s;v3.y*=s;v3.z*=s;v3.w*=s;
    asm volatile("red.global.add.v4.f32 [%0], {%1,%2,%3,%4};"::"l"(d+0),"f"(v0.x),"f"(v0.y),"f"(v0.z),"f"(v0.w):"memory");
    asm volatile("red.global.add.v4.f32 [%0], {%1,%2,%3,%4};"::"l"(d+4),"f"(v1.x),"f"(v1.y),"f"(v1.z),"f"(v1.w):"memory");
    asm volatile("red.global.add.v4.f32 [%0], {%1,%2,%3,%4};"::"l"(d+8),"f"(v2.x),"f"(v2.y),"f"(v2.z),"f"(v2.w):"memory");
    asm volatile("red.global.add.v4.f32 [%0], {%1,%2,%3,%4};"::"l"(d+12),"f"(v3.x),"f"(v3.y),"f"(v3.z),"f"(v3.w):"memory");
}
__global__ void k_scat1(float* __restrict__ dst, const float* __restrict__ src,
                        const int* __restrict__ row, const int* __restrict__ col, int e){
    int i=blockIdx.x*blockDim.x+threadIdx.x;
    if(i<e){
        float v=src[row[i]];
        if(v!=0.0f)
            asm volatile("red.global.add.f32 [%0], %1;"::"l"(&dst[col[i]]),"f"(v):"memory");
    }
}

// ---------------- radix select (smem-staged serial scans) ----------------
__global__ void k_find1(int kk){
    __shared__ int cs[256]; __shared__ int fine[256]; __shared__ int sel;
    int t=threadIdx.x, s=0;
    for(int b=0;b<256;b++) s+=g_hist[t*256+b];
    cs[t]=s; __syncthreads();
    if(t==0){
        int acc=0, c;
        for(c=255;c>0;c--){ if(acc+cs[c]>=kk) break; acc+=cs[c]; }
        sel=c; g_before=acc;
    }
    __syncthreads();
    int c=sel;
    fine[t]=g_hist[c*256+t];
    __syncthreads();
    if(t==0){
        int acc=g_before;
        for(int b=255;b>=0;b--){
            acc+=fine[b];
            if(acc>=kk){ g_selB=c*256+b; g_before=acc-fine[b]; return; }
        }
        g_selB=c*256; 
    }
}
__global__ void k_hist2(int n){
    int i=blockIdx.x*blockDim.x+threadIdx.x;
    if(i<n){ unsigned u=g_key[i]; if((int)(u>>16)==g_selB) atomicAdd(&g_hist2[u&0xFFFFu],1); }
}
__global__ void k_find2(int kk){
    __shared__ int cs[256]; __shared__ int fine[256]; __shared__ int sel;
    int t=threadIdx.x, s=0;
    for(int b=0;b<256;b++) s+=g_hist2[t*256+b];
    cs[t]=s; __syncthreads();
    int rem=kk-g_before;
    if(t==0){
        int acc=0, c;
        for(c=255;c>0;c--){ if(acc+cs[c]>=rem) break; acc+=cs[c]; }
        sel=c; g_needed=acc;     // temp: count above bucket c
    }
    __syncthreads();
    int c=sel;
    fine[t]=g_hist2[c*256+t];
    __syncthreads();
    if(t==0){
        int acc=g_needed;
        for(int b=255;b>=0;b--){
            acc+=fine[b];
            if(acc>=rem){
                g_T=((unsigned)g_selB<<16)|(unsigned)(c*256+b);
                g_needed=rem-(acc-fine[b]);
                return;
            }
        }
        g_T=(unsigned)g_selB<<16; g_needed=0;
    }
}
// mark kept + collect ties + masked-index compaction
__global__ void k_markmik(const int* __restrict__ mask, int n){
    int i=blockIdx.x*blockDim.x+threadIdx.x;
    if(i<n){
        unsigned u=g_key[i];
        g_kept[i]=(u>g_T)?1.0f:0.0f;
        if(u==g_T){ int p=atomicAdd(&g_tcnt,1); if(p<4096) g_tie[p]=i; }
        int p=-1;
        if(mask[i]!=0){ p=atomicAdd(&g_M,1); g_mi[p]=i; }
        g_pos[i]=p;
    }
}
__global__ void k_tiefix(){
    int need=g_needed, tc=g_tcnt; if(tc>4096) tc=4096;
    for(int s=0;s<need&&s<tc;s++){
        int mb=s;
        for(int j=s+1;j<tc;j++) if(g_tie[j]<g_tie[mb]) mb=j;
        int tmp=g_tie[s]; g_tie[s]=g_tie[mb]; g_tie[mb]=tmp;
        g_kept[g_tie[s]]=1.0f;
    }
}

// ---------------- hash lookup → diagonal of M^2 ----------------
__global__ void k_ccK(const int* __restrict__ row, const int* __restrict__ col, int e, int n){
    int i=blockIdx.x*blockDim.x+threadIdx.x;
    if(i>=e) return;
    unsigned long long key=(unsigned long long)col[i]*(unsigned)n+(unsigned)row[i];
    unsigned h=hmix(key);
    int cnt=0;
    while(true){
        unsigned long long k2=g_hk[h];
        if(k2==key){ cnt=g_hc[h]; break; }
        if(k2==~0ull) break;
        h=(h+1)&HASHMASK;
    }
    if(cnt) atomicAdd(&g_cc[row[i]],cnt);
}
__global__ void k_dinvPk(int n){
    int i=blockIdx.x*blockDim.x+threadIdx.x;
    if(i<n){
        float degP=g_tdeg[i]+2.0f*g_sdeg[i]+2.0f-(float)g_cc[i];
        g_dinvP[i]=(g_kept[i]>0.5f)?rsqrtf(degP):0.0f;
    }
}
__global__ void k_x2up4(const float* __restrict__ b1, int n16){
    int i=blockIdx.x*blockDim.x+threadIdx.x;
    if(i<n16){
        int r=i>>4;
        float dp=g_dinvP[r];
        float4 v=make_float4(0,0,0,0);
        if(dp!=0.0f){
            float cf=(2.0f-(float)g_cc[r])*dp;
            float4 t=((const float4*)g_Tb)[i];
            float4 s=((const float4*)g_S)[i];
            float4 h=((const float4*)g_H)[i];
            float4 bv=*(const float4*)&b1[(i&15)*4];
            v.x=fmaxf(dp*(t.x+2.0f*s.x+cf*h.x)+bv.x,0.f);
            v.y=fmaxf(dp*(t.y+2.0f*s.y+cf*h.y)+bv.y,0.f);
            v.z=fmaxf(dp*(t.z+2.0f*s.z+cf*h.z)+bv.z,0.f);
            v.w=fmaxf(dp*(t.w+2.0f*s.w+cf*h.w)+bv.w,0.f);
        }
        ((float4*)g_B2)[i]=v;
    }
}
__global__ void k_xin4(int n16){
    int i=blockIdx.x*blockDim.x+threadIdx.x;
    if(i<n16){
        int r=i>>4, fq=i&15;
        int p=g_pos[r];
        float4 v=(p>=0)?((const float4*)g_B1)[p*16+fq]:((const float4*)g_X1)[i];
        float4 u=((const float4*)g_B2)[i];
        v.x+=u.x; v.y+=u.y; v.z+=u.z; v.w+=u.w;
        ((float4*)g_RES)[i]=v;
    }
}
__global__ void k_scat_out4(float* __restrict__ out, int n16){
    int i=blockIdx.x*blockDim.x+threadIdx.x;
    if(i<n16){
        int p=i>>4;
        if(p<g_M) *(float4*)&out[g_mi[p]*64+(i&15)*4]=((const float4*)g_B1)[i];
    }
}

// ------- paired-weight smem loader ----------------------------------------------
__device__ __forceinline__ void load_paired(float* sW, const float* __restrict__ W, int tid){
    for(int i=tid*4;i<256*64;i+=256*4){
        int g=i>>6, f0=i&63;
        int j=g>>5, lg=g&31, kp=j>>1, half=j&1;
        int dbase=kp*64+lg*2+half;
        float4 w=*(const float4*)&W[i];
        sW[dbase+(f0+0)*256]=w.x; sW[dbase+(f0+1)*256]=w.y;
        sW[dbase+(f0+2)*256]=w.z; sW[dbase+(f0+3)*256]=w.w;
    }
}

// ------- Gx precompute ----------------------------------------------------------
__global__ __launch_bounds__(256) void k_gx(const float* __restrict__ Xsrc,
    const float* __restrict__ Wih, const float* __restrict__ bih,
    const float* __restrict__ bhh, int n){
    extern __shared__ float sWi[];
    int tid=threadIdx.x;
    load_paired(sWi,Wih,tid);
    __syncthreads();
    int wid=tid>>5, lane=tid&31;
    unsigned long long bs[4];
    #pragma unroll
    for(int kp=0;kp<4;kp++){
        float blo=bih[lane+64*kp]+bhh[lane+64*kp];
        float bhi=bih[lane+64*kp+32]+bhh[lane+64*kp+32];
        PACK2(bs[kp],blo,bhi);
    }
    unsigned long long* G=g_GX;
    for(int r0=(blockIdx.x*8+wid)*2; r0<n; r0+=gridDim.x*16){
        int r1=r0+1; bool has1=r1<n;
        float xl0=Xsrc[r0*64+lane], xh0=Xsrc[r0*64+lane+32];
        float xl1=has1?Xsrc[r1*64+lane]:0.0f, xh1=has1?Xsrc[r1*64+lane+32]:0.0f;
        unsigned long long a0[4],a1[4];
        #pragma unroll
        for(int kp=0;kp<4;kp++){ a0[kp]=bs[kp]; a1[kp]=bs[kp]; }
        #define GX_F(F,X0,X1S) { \
            const unsigned long long* wp=(const unsigned long long*)&sWi[(F)*256]+lane; \
            unsigned long long w0=wp[0],w1=wp[32],w2=wp[64],w3=wp[96]; \
            float xv0=__shfl_sync(0xffffffffu,X0,(F)&31); \
            float xv1=__shfl_sync(0xffffffffu,X1S,(F)&31); \
            unsigned long long p0,p1; BCAST2(p0,xv0); BCAST2(p1,xv1); \
            FMA2(a0[0],p0,w0); FMA2(a0[1],p0,w1); FMA2(a0[2],p0,w2); FMA2(a0[3],p0,w3); \
            FMA2(a1[0],p1,w0); FMA2(a1[1],p1,w1); FMA2(a1[2],p1,w2); FMA2(a1[3],p1,w3); }
        #pragma unroll 8
        for(int f=0;f<32;f++) GX_F(f,xl0,xl1)
        #pragma unroll 8
        for(int f=32;f<64;f++) GX_F(f,xh0,xh1)
        #undef GX_F
        #pragma unroll
        for(int kp=0;kp<4;kp++){
            G[r0*128+kp*32+lane]=a0[kp];
            if(has1) G[r1*128+kp*32+lane]=a1[kp];
        }
    }
}

// ------- LSTM recurrence (h-part only) ------------------------------------------
__global__ __launch_bounds__(256) void k_lstm(
    const float* __restrict__ Whh, const float* __restrict__ bih,
    const float* __restrict__ bhh, float* __restrict__ out){
    extern __shared__ float sWh[];
    int tid=threadIdx.x;
    load_paired(sWh,Whh,tid);
    __syncthreads();
    int wid=tid>>5, lane=tid&31;
    int M=g_M;
    unsigned long long bs[4];
    #pragma unroll
    for(int kp=0;kp<4;kp++){
        float blo=bih[lane+64*kp]+bhh[lane+64*kp];
        float bhi=bih[lane+64*kp+32]+bhh[lane+64*kp+32];
        PACK2(bs[kp],blo,bhi);
    }
    const unsigned long long* G=g_GX;
    for(int base=(blockIdx.x*8+wid)*4; base<M; base+=gridDim.x*32){
        int rid[4];
        #pragma unroll
        for(int nn=0;nn<4;nn++) rid[nn]=(base+nn<M)?g_mi[base+nn]:-1;
        float hl[4]={0,0,0,0}, hh[4]={0,0,0,0}, cl[4]={0,0,0,0}, ch[4]={0,0,0,0};
        for(int t=0;t<5;t++){
            unsigned long long acc[4][4];
            #pragma unroll
            for(int nn=0;nn<4;nn++){
                int sr=rid[nn]-4+t;
                bool ok=(rid[nn]>=0)&&(sr>=0);
                const unsigned long long* gp=G+(ok?sr:0)*128+lane;
                #pragma unroll
                for(int kp=0;kp<4;kp++) acc[nn][kp]=ok?gp[kp*32]:bs[kp];
            }
            if(t>0){
                #define LSTM_F(F,HS) { \
                    const unsigned long long* whP=(const unsigned long long*)&sWh[(F)*256]+lane; \
                    unsigned long long w0=whP[0],w1=whP[32],w2=whP[64],w3=whP[96]; \
                    _Pragma("unroll") \
                    for(int nn=0;nn<4;nn++){ \
                        float hv=__shfl_sync(0xffffffffu,HS[nn],(F)&31); \
                        unsigned long long hp; BCAST2(hp,hv); \
                        FMA2(acc[nn][0],hp,w0); FMA2(acc[nn][1],hp,w1); \
                        FMA2(acc[nn][2],hp,w2); FMA2(acc[nn][3],hp,w3); \
                    } }
                #pragma unroll 8
                for(int f=0;f<32;f++) LSTM_F(f,hl)
                #pragma unroll 8
                for(int f=32;f<64;f++) LSTM_F(f,hh)
                #undef LSTM_F
            }
            #pragma unroll
            for(int nn=0;nn<4;nn++){
                float il,ih,fl,fh,gl,gh,ol,oh;
                UNPACK2(il,ih,acc[nn][0]);
                UNPACK2(fl,fh,acc[nn][1]);
                UNPACK2(gl,gh,acc[nn][2]);
                UNPACK2(ol,oh,acc[nn][3]);
                cl[nn]=sigf(fl)*cl[nn]+sigf(il)*tanhf(gl); hl[nn]=sigf(ol)*tanhf(cl[nn]);
                ch[nn]=sigf(fh)*ch[nn]+sigf(ih)*tanhf(gh); hh[nn]=sigf(oh)*tanhf(ch[nn]);
            }
        }
        #pragma unroll
        for(int nn=0;nn<4;nn++){
            if(rid[nn]>=0){
                out[(base+nn)*64+lane]=hl[nn];
                out[(base+nn)*64+lane+32]=hh[nn];
            }
        }
    }
}

// ---------------- host ----------------
extern "C" void kernel_launch(void* const* d_in, const int* in_sizes, int n_in,
                              void* d_out, int out_size){
    const float* x=(const float*)d_in[0];
    const int* row=(const int*)d_in[1];
    const int* mask=(const int*)d_in[2];
    const float* W0=(const float*)d_in[3];  const float* b0=(const float*)d_in[4];
    const float* W1=(const float*)d_in[5];  const float* b1=(const float*)d_in[6];
    const float* pw=(const float*)d_in[7];
    const float* Wu=(const float*)d_in[8];  const float* bu=(const float*)d_in[9];
    const float* l0wih=(const float*)d_in[10]; const float* l0whh=(const float*)d_in[11];
    const float* l0bih=(const float*)d_in[12]; const float* l0bhh=(const float*)d_in[13];
    const float* fwih=(const float*)d_in[14];  const float* fwhh=(const float*)d_in[15];
    const float* fbih=(const float*)d_in[16];  const float* fbhh=(const float*)d_in[17];
    float* out=(float*)d_out;

    int n=in_sizes[0]/32;
    int e=in_sizes[1]/2;
    const int* col=row+e;
    int kk=(n+1)/2;
    int n16=n*16;
    int GN=(n+255)/256, GN16=(n16+255)/256, GE=(e+255)/256;
    int GS=(e*4+255)/256;

    static int smem_set=0;
    if(!smem_set){
        cudaFuncSetAttribute(k_lstm, cudaFuncAttributeMaxDynamicSharedMemorySize, WSMEM);
        cudaFuncSetAttribute(k_gx,   cudaFuncAttributeMaxDynamicSharedMemorySize, WSMEM);
        smem_set=1;
    }

    float *dX1,*dH,*dB1,*dS,*dTb,*dRES,*dsdeg,*dtdeg;
    int *dicnt;
    cudaGetSymbolAddress((void**)&dX1,g_X1);
    cudaGetSymbolAddress((void**)&dH,g_H);
    cudaGetSymbolAddress((void**)&dB1,g_B1);
    cudaGetSymbolAddress((void**)&dS,g_S);
    cudaGetSymbolAddress((void**)&dTb,g_Tb);
    cudaGetSymbolAddress((void**)&dRES,g_RES);
    cudaGetSymbolAddress((void**)&dsdeg,g_sdeg);
    cudaGetSymbolAddress((void**)&dtdeg,g_tdeg);
    cudaGetSymbolAddress((void**)&dicnt,g_icnt);
    float *dkept; cudaGetSymbolAddress((void**)&dkept,g_kept);
    float *dscore; cudaGetSymbolAddress((void**)&dscore,g_score);
    float *ddinvP; cudaGetSymbolAddress((void**)&ddinvP,g_dinvP);
    float *ddinv0; cudaGetSymbolAddress((void**)&ddinv0,g_dinv0);

    // fused init
    k_init<<<(int)(HASHSZ/256),256>>>(pw,n,n16);

    // conv0: x1 = relu(GCN(x)) fused with topk score+hist
    k_edge0<<<GE,256>>>(row,col,e,n);
    k_gemm<32><<<(n+15)/16,256>>>(x,W0,(const float*)0,dH,dB1,dicnt,n); // H + self + dinv0
    k_scat64<<<GS,256>>>(dB1,dH,ddinv0,row,col,e);
    k_fin_score<<<(n*32+255)/256,256>>>(dB1,b0,pw,n);

    // topk select
    k_find1<<<1,256>>>(kk);
    k_hist2<<<GN,256>>>(n);
    k_find2<<<1,256>>>(kk);
    k_markmik<<<GN,256>>>(mask,n);
    k_tiefix<<<1,1>>>();

    // diagonal of M^2 via hash
    k_ccK<<<GE,256>>>(row,col,e,n);

    // pooled degrees
    k_scat1<<<GE,256>>>(dsdeg,dkept,row,col,e);
    k_scat1<<<GE,256>>>(dtdeg,dsdeg,row,col,e);
    k_dinvPk<<<GN,256>>>(n);

    // conv1 on pooled graph (S/Tb pre-zeroed in k_init)
    k_gemm<64><<<(n+15)/16,256>>>(dX1,W1,dscore,dH,(float*)0,(const int*)0,n); // h2
    k_scat64<<<GS,256>>>(dS,dH,ddinvP,row,col,e);                 // s
    k_scat64<<<GS,256>>>(dTb,dS,(const float*)0,row,col,e);       // t
    k_x2up4<<<GN16,256>>>(b1,n16);                                // UP -> B2

    // LSTM0
    k_gx<<<PGRID,256,WSMEM>>>(dX1,l0wih,l0bih,l0bhh,n);
    k_lstm<<<PGRID,256,WSMEM>>>(l0whh,l0bih,l0bhh,dB1);           // h0 -> B1
    k_xin4<<<GN16,256>>>(n16);                                    // RES

    // final GCN -> out
    k_gemm<64><<<(n+15)/16,256>>>(dRES,Wu,(const float*)0,dH,dB1,(const int*)0,n);
    k_scat64<<<GS,256>>>(dB1,dH,ddinv0,row,col,e);
    k_fin4<<<GN16,256>>>((float4*)out,(const float4*)dB1,bu,n16,0);

    // final LSTM
    k_gx<<<PGRID,256,WSMEM>>>(out,fwih,fbih,fbhh,n);
    k_lstm<<<PGRID,256,WSMEM>>>(fwhh,fbih,fbhh,dB1);
    k_scat_out4<<<GN16,256>>>(out,n16);
}

// round 7
// speedup vs baseline: 1.7318x; 1.1116x over previous
#include <cuda_runtime.h>
#include <math.h>

#define NMAX 50000
#define EMAX 400000
#define HASHSZ (1u<<21)
#define HASHMASK (HASHSZ-1u)
#define WSMEM (64*256*4)
#define PGRID 444

// ---------------- scratch ----------------
__device__ float g_X1 [NMAX*64];
__device__ float g_H  [NMAX*64];
__device__ float g_B1 [NMAX*64];
__device__ float g_B2 [NMAX*64];
__device__ float g_RES[NMAX*64];
__device__ float g_S  [NMAX*64];
__device__ unsigned long long g_GX[NMAX*128];
__device__ float g_dinv0[NMAX];
__device__ float g_dinvP[NMAX];
__device__ float g_score[NMAX];
__device__ float g_kept[NMAX];
__device__ float g_sdeg[NMAX];
__device__ unsigned g_key[NMAX];
__device__ int   g_icnt[NMAX];
__device__ int   g_cc[NMAX];
__device__ int   g_mi[NMAX];
__device__ int   g_pos[NMAX];
__device__ int   g_off[NMAX+1];
__device__ int   g_cur[NMAX];
__device__ int   g_eidx[EMAX];
__device__ int   g_bsum[256];
__device__ int   g_bscan[256];
__device__ int   g_hist[65536];
__device__ int   g_hist2[65536];
__device__ int   g_tie[4096];
__device__ int   g_M, g_tcnt, g_selB, g_before, g_needed;
__device__ unsigned g_T;
__device__ float g_pwnorm;
__device__ unsigned long long g_hk[HASHSZ];
__device__ int   g_hc[HASHSZ];

__device__ __forceinline__ float sigf(float x){ return 1.0f/(1.0f+expf(-x)); }

#define FMA2(A,B,C) asm("fma.rn.f32x2 %0,%1,%2,%0;":"+l"(A):"l"(B),"l"(C))
#define PACK2(D,LO,HI) asm("mov.b64 %0,{%1,%2};":"=l"(D):"f"(LO),"f"(HI))
#define BCAST2(D,V) asm("mov.b64 %0,{%1,%1};":"=l"(D):"f"(V))
#define UNPACK2(LO,HI,S) asm("mov.b64 {%0,%1},%2;":"=f"(LO),"=f"(HI):"l"(S))

// ------- fused init ---------------------------------------------------------------
__global__ void k_init(const float* __restrict__ pw, int n){
    int i=blockIdx.x*blockDim.x+threadIdx.x;
    if(i<(int)HASHSZ){ g_hk[i]=~0ull; g_hc[i]=0; }
    if(i<n){ g_icnt[i]=0; g_cc[i]=0; }
    if(i<65536){ g_hist[i]=0; g_hist2[i]=0; }
    if(i==0){ g_M=0; g_tcnt=0; }
    if(blockIdx.x==0&&threadIdx.x<32){
        int l=threadIdx.x;
        float v=pw[l]*pw[l]+pw[l+32]*pw[l+32];
        for(int o=16;o;o>>=1) v+=__shfl_down_sync(0xffffffffu,v,o);
        if(l==0) g_pwnorm=sqrtf(v);
    }
}

// ------- edge pass: in-degree + hash insert ---------------------------------------
__device__ __forceinline__ unsigned hmix(unsigned long long x){
    x^=x>>30; x*=0xbf58476d1ce4e5b9ull;
    x^=x>>27; x*=0x94d049bb133111ebull;
    x^=x>>31;
    return (unsigned)x&HASHMASK;
}
__global__ void k_edge0(const int* __restrict__ row, const int* __restrict__ col, int e, int n){
    int i=blockIdx.x*blockDim.x+threadIdx.x;
    if(i>=e) return;
    atomicAdd(&g_icnt[col[i]],1);
    unsigned long long key=(unsigned long long)row[i]*(unsigned)n+(unsigned)col[i];
    unsigned h=hmix(key);
    while(true){
        unsigned long long prev=atomicCAS(&g_hk[h],~0ull,key);
        if(prev==~0ull||prev==key){ atomicAdd(&g_hc[h],1); break; }
        h=(h+1)&HASHMASK;
    }
}

// ------- CSR build: 2-level exclusive scan + placement ----------------------------
__global__ void k_scan1(int n){
    __shared__ int s[256];
    int t=threadIdx.x, i=blockIdx.x*256+t;
    int v=(i<n)?g_icnt[i]:0;
    if(i<n) g_dinv0[i]=rsqrtf((float)v+2.0f);
    s[t]=v; __syncthreads();
    for(int o=128;o;o>>=1){ if(t<o) s[t]+=s[t+o]; __syncthreads(); }
    if(t==0) g_bsum[blockIdx.x]=s[0];
}
__global__ void k_scan2(int nb){
    __shared__ int s[256];
    int t=threadIdx.x;
    int v=(t<nb)?g_bsum[t]:0;
    s[t]=v; __syncthreads();
    for(int o=1;o<256;o<<=1){
        int u=(t>=o)?s[t-o]:0; __syncthreads();
        s[t]+=u; __syncthreads();
    }
    g_bscan[t]=s[t]-v;
}
__global__ void k_scan3(int n, int e){
    __shared__ int s[256];
    int t=threadIdx.x, i=blockIdx.x*256+t;
    int v=(i<n)?g_icnt[i]:0;
    s[t]=v; __syncthreads();
    for(int o=1;o<256;o<<=1){
        int u=(t>=o)?s[t-o]:0; __syncthreads();
        s[t]+=u; __syncthreads();
    }
    if(i<n){
        int off=g_bscan[blockIdx.x]+s[t]-v;
        g_off[i]=off; g_cur[i]=off;
        if(i==n-1) g_off[n]=e;
    }
}
__global__ void k_place(const int* __restrict__ row, const int* __restrict__ col, int e){
    int i=blockIdx.x*blockDim.x+threadIdx.x;
    if(i<e){
        int p=atomicAdd(&g_cur[col[i]],1);
        g_eidx[p]=row[i];
    }
}

// ------- dense GEMM: out = scale1?.(X(row-scaled rs)@W), out2 = scale2.(...) -----
template<int K>
__global__ void k_gemm(const float* __restrict__ X, const float* __restrict__ W,
                       const float* __restrict__ rs, float* __restrict__ out,
                       const float* __restrict__ scale1,
                       float* __restrict__ out2, const float* __restrict__ scale2, int n){
    __shared__ float sW[K*64];
    __shared__ float sX[16*K];
    int tid=threadIdx.x;
    for(int i=tid;i<K*64;i+=256) sW[i]=W[i];
    int r0=blockIdx.x*16;
    for(int i=tid;i<16*K;i+=256){
        int rr=i/K, kk=i%K, row=r0+rr;
        float v=0.0f;
        if(row<n){ v=X[row*K+kk]; if(rs) v*=rs[row]; }
        sX[i]=v;
    }
    __syncthreads();
    int c=tid&63, rg=tid>>6;
    float a0=0,a1=0,a2=0,a3=0;
    #pragma unroll 8
    for(int kk=0;kk<K;kk++){
        float w=sW[kk*64+c];
        a0+=sX[(rg*4+0)*K+kk]*w;
        a1+=sX[(rg*4+1)*K+kk]*w;
        a2+=sX[(rg*4+2)*K+kk]*w;
        a3+=sX[(rg*4+3)*K+kk]*w;
    }
    int row=r0+rg*4;
    #pragma unroll
    for(int rr=0;rr<4;rr++){
        float a=(rr==0)?a0:(rr==1)?a1:(rr==2)?a2:a3;
        if(row+rr<n){
            out[(row+rr)*64+c]=scale1?scale1[row+rr]*a:a;
            if(out2) out2[(row+rr)*64+c]=scale2[row+rr]*a;
        }
    }
}

// ------- GCN gather (warp/node): out = dinv0[c]*(Σ_in Hs[r] + 2*Hs[c]) + b -------
// fused variants: relu+score (conv0) or plain (final conv)
template<int MODE>   // 0 = final (no relu), 1 = conv0 (relu + score + hist)
__global__ void k_gcng(const float* __restrict__ Hs, const float* __restrict__ b,
                       const float* __restrict__ pw, float* __restrict__ out, int n){
    int node=(blockIdx.x*blockDim.x+threadIdx.x)>>5;
    int l=threadIdx.x&31;
    if(node>=n) return;
    float alo=2.0f*Hs[node*64+l], ahi=2.0f*Hs[node*64+l+32];
    int s0=g_off[node], s1=g_off[node+1];
    for(int j=s0;j<s1;j++){
        int r=g_eidx[j];
        alo+=Hs[r*64+l];
        ahi+=Hs[r*64+l+32];
    }
    float d=g_dinv0[node];
    float vlo=d*alo+b[l], vhi=d*ahi+b[l+32];
    if(MODE==1){
        vlo=fmaxf(vlo,0.0f); vhi=fmaxf(vhi,0.0f);
        out[node*64+l]=vlo; out[node*64+l+32]=vhi;
        float s=vlo*pw[l]+vhi*pw[l+32];
        for(int o=16;o;o>>=1) s+=__shfl_down_sync(0xffffffffu,s,o);
        if(l==0){
            float sc=tanhf(s/g_pwnorm);
            g_score[node]=sc;
            unsigned bb=__float_as_uint(sc);
            unsigned key=(bb&0x80000000u)?~bb:(bb|0x80000000u);
            g_key[node]=key;
            atomicAdd(&g_hist[key>>16],1);
        }
    }else{
        out[node*64+l]=vlo; out[node*64+l+32]=vhi;
    }
}
// s[c] = Σ_in m[r]
__global__ void k_sg(const float* __restrict__ m, float* __restrict__ s, int n){
    int node=(blockIdx.x*blockDim.x+threadIdx.x)>>5;
    int l=threadIdx.x&31;
    if(node>=n) return;
    float alo=0.0f, ahi=0.0f;
    int s0=g_off[node], s1=g_off[node+1];
    for(int j=s0;j<s1;j++){
        int r=g_eidx[j];
        alo+=m[r*64+l];
        ahi+=m[r*64+l+32];
    }
    s[node*64+l]=alo; s[node*64+l+32]=ahi;
}
// t gather + up epilogue: B2 = relu(dp*(Σ_in s[r] + 2*s[c] + cf*h2[c]) + b1), 0 if dp=0
__global__ void k_tup(const float* __restrict__ s, const float* __restrict__ h2,
                      const float* __restrict__ b1, float* __restrict__ up, int n){
    int node=(blockIdx.x*blockDim.x+threadIdx.x)>>5;
    int l=threadIdx.x&31;
    if(node>=n) return;
    float dp=g_dinvP[node];
    if(dp==0.0f){
        up[node*64+l]=0.0f; up[node*64+l+32]=0.0f;
        return;
    }
    float alo=0.0f, ahi=0.0f;
    int s0=g_off[node], s1=g_off[node+1];
    for(int j=s0;j<s1;j++){
        int r=g_eidx[j];
        alo+=s[r*64+l];
        ahi+=s[r*64+l+32];
    }
    float cf=(2.0f-(float)g_cc[node])*dp;
    float vlo=fmaxf(dp*(alo+2.0f*s[node*64+l]   +cf*h2[node*64+l])   +b1[l],   0.0f);
    float vhi=fmaxf(dp*(ahi+2.0f*s[node*64+l+32]+cf*h2[node*64+l+32])+b1[l+32],0.0f);
    up[node*64+l]=vlo; up[node*64+l+32]=vhi;
}

// ---------------- radix select ----------------
__global__ void k_find1(int kk){
    __shared__ int cs[256]; __shared__ int fine[256]; __shared__ int sel;
    int t=threadIdx.x, s=0;
    for(int b=0;b<256;b++) s+=g_hist[t*256+b];
    cs[t]=s; __syncthreads();
    if(t==0){
        int acc=0, c;
        for(c=255;c>0;c--){ if(acc+cs[c]>=kk) break; acc+=cs[c]; }
        sel=c; g_before=acc;
    }
    __syncthreads();
    int c=sel;
    fine[t]=g_hist[c*256+t];
    __syncthreads();
    if(t==0){
        int acc=g_before;
        for(int b=255;b>=0;b--){
            acc+=fine[b];
            if(acc>=kk){ g_selB=c*256+b; g_before=acc-fine[b]; return; }
        }
        g_selB=c*256;
    }
}
__global__ void k_hist2k(int n){
    int i=blockIdx.x*blockDim.x+threadIdx.x;
    if(i<n){ unsigned u=g_key[i]; if((int)(u>>16)==g_selB) atomicAdd(&g_hist2[u&0xFFFFu],1); }
}
__global__ void k_find2(int kk){
    __shared__ int cs[256]; __shared__ int fine[256]; __shared__ int sel;
    int t=threadIdx.x, s=0;
    for(int b=0;b<256;b++) s+=g_hist2[t*256+b];
    cs[t]=s; __syncthreads();
    int rem=kk-g_before;
    if(t==0){
        int acc=0, c;
        for(c=255;c>0;c--){ if(acc+cs[c]>=rem) break; acc+=cs[c]; }
        sel=c; g_needed=acc;
    }
    __syncthreads();
    int c=sel;
    fine[t]=g_hist2[c*256+t];
    __syncthreads();
    if(t==0){
        int acc=g_needed;
        for(int b=255;b>=0;b--){
            acc+=fine[b];
            if(acc>=rem){
                g_T=((unsigned)g_selB<<16)|(unsigned)(c*256+b);
                g_needed=rem-(acc-fine[b]);
                return;
            }
        }
        g_T=(unsigned)g_selB<<16; g_needed=0;
    }
}
__global__ void k_markmik(const int* __restrict__ mask, int n){
    int i=blockIdx.x*blockDim.x+threadIdx.x;
    if(i<n){
        unsigned u=g_key[i];
        g_kept[i]=(u>g_T)?1.0f:0.0f;
        if(u==g_T){ int p=atomicAdd(&g_tcnt,1); if(p<4096) g_tie[p]=i; }
        int p=-1;
        if(mask[i]!=0){ p=atomicAdd(&g_M,1); g_mi[p]=i; }
        g_pos[i]=p;
    }
}
__global__ void k_tiefix(){
    int need=g_needed, tc=g_tcnt; if(tc>4096) tc=4096;
    for(int s=0;s<need&&s<tc;s++){
        int mb=s;
        for(int j=s+1;j<tc;j++) if(g_tie[j]<g_tie[mb]) mb=j;
        int tmp=g_tie[s]; g_tie[s]=g_tie[mb]; g_tie[mb]=tmp;
        g_kept[g_tie[s]]=1.0f;
    }
}

// ---------------- hash lookup → diagonal of M^2 ----------------
__global__ void k_ccK(const int* __restrict__ row, const int* __restrict__ col, int e, int n){
    int i=blockIdx.x*blockDim.x+threadIdx.x;
    if(i>=e) return;
    unsigned long long key=(unsigned long long)col[i]*(unsigned)n+(unsigned)row[i];
    unsigned h=hmix(key);
    int cnt=0;
    while(true){
        unsigned long long k2=g_hk[h];
        if(k2==key){ cnt=g_hc[h]; break; }
        if(k2==~0ull) break;
        h=(h+1)&HASHMASK;
    }
    if(cnt) atomicAdd(&g_cc[row[i]],cnt);
}
// sdeg[c]=Σ_in kept[r]  (thread/node)
__global__ void k_sdeg(int n){
    int i=blockIdx.x*blockDim.x+threadIdx.x;
    if(i>=n) return;
    float s=0.0f;
    for(int j=g_off[i];j<g_off[i+1];j++) s+=g_kept[g_eidx[j]];
    g_sdeg[i]=s;
}
// dinvP[c]: tdeg inline gather of sdeg
__global__ void k_dinvPk(int n){
    int i=blockIdx.x*blockDim.x+threadIdx.x;
    if(i>=n) return;
    float td=0.0f;
    for(int j=g_off[i];j<g_off[i+1];j++) td+=g_sdeg[g_eidx[j]];
    float degP=td+2.0f*g_sdeg[i]+2.0f-(float)g_cc[i];
    g_dinvP[i]=(g_kept[i]>0.5f)?rsqrtf(degP):0.0f;
}
__global__ void k_xin4(int n16){
    int i=blockIdx.x*blockDim.x+threadIdx.x;
    if(i<n16){
        int r=i>>4, fq=i&15;
        int p=g_pos[r];
        float4 v=(p>=0)?((const float4*)g_B1)[p*16+fq]:((const float4*)g_X1)[i];
        float4 u=((const float4*)g_B2)[i];
        v.x+=u.x; v.y+=u.y; v.z+=u.z; v.w+=u.w;
        ((float4*)g_RES)[i]=v;
    }
}
__global__ void k_scat_out4(float* __restrict__ out, int n16){
    int i=blockIdx.x*blockDim.x+threadIdx.x;
    if(i<n16){
        int p=i>>4;
        if(p<g_M) *(float4*)&out[g_mi[p]*64+(i&15)*4]=((const float4*)g_B1)[i];
    }
}

// ------- paired-weight smem loader ------------------------------------------------
__device__ __forceinline__ void load_paired(float* sW, const float* __restrict__ W, int tid){
    for(int i=tid*4;i<256*64;i+=256*4){
        int g=i>>6, f0=i&63;
        int j=g>>5, lg=g&31, kp=j>>1, half=j&1;
        int dbase=kp*64+lg*2+half;
        float4 w=*(const float4*)&W[i];
        sW[dbase+(f0+0)*256]=w.x; sW[dbase+(f0+1)*256]=w.y;
        sW[dbase+(f0+2)*256]=w.z; sW[dbase+(f0+3)*256]=w.w;
    }
}

// ------- Gx precompute ------------------------------------------------------------
__global__ __launch_bounds__(256) void k_gx(const float* __restrict__ Xsrc,
    const float* __restrict__ Wih, const float* __restrict__ bih,
    const float* __restrict__ bhh, int n){
    extern __shared__ float sWi[];
    int tid=threadIdx.x;
    load_paired(sWi,Wih,tid);
    __syncthreads();
    int wid=tid>>5, lane=tid&31;
    unsigned long long bs[4];
    #pragma unroll
    for(int kp=0;kp<4;kp++){
        float blo=bih[lane+64*kp]+bhh[lane+64*kp];
        float bhi=bih[lane+64*kp+32]+bhh[lane+64*kp+32];
        PACK2(bs[kp],blo,bhi);
    }
    unsigned long long* G=g_GX;
    for(int r0=(blockIdx.x*8+wid)*2; r0<n; r0+=gridDim.x*16){
        int r1=r0+1; bool has1=r1<n;
        float xl0=Xsrc[r0*64+lane], xh0=Xsrc[r0*64+lane+32];
        float xl1=has1?Xsrc[r1*64+lane]:0.0f, xh1=has1?Xsrc[r1*64+lane+32]:0.0f;
        unsigned long long a0[4],a1[4];
        #pragma unroll
        for(int kp=0;kp<4;kp++){ a0[kp]=bs[kp]; a1[kp]=bs[kp]; }
        #define GX_F(F,X0,X1S) { \
            const unsigned long long* wp=(const unsigned long long*)&sWi[(F)*256]+lane; \
            unsigned long long w0=wp[0],w1=wp[32],w2=wp[64],w3=wp[96]; \
            float xv0=__shfl_sync(0xffffffffu,X0,(F)&31); \
            float xv1=__shfl_sync(0xffffffffu,X1S,(F)&31); \
            unsigned long long p0,p1; BCAST2(p0,xv0); BCAST2(p1,xv1); \
            FMA2(a0[0],p0,w0); FMA2(a0[1],p0,w1); FMA2(a0[2],p0,w2); FMA2(a0[3],p0,w3); \
            FMA2(a1[0],p1,w0); FMA2(a1[1],p1,w1); FMA2(a1[2],p1,w2); FMA2(a1[3],p1,w3); }
        #pragma unroll 8
        for(int f=0;f<32;f++) GX_F(f,xl0,xl1)
        #pragma unroll 8
        for(int f=32;f<64;f++) GX_F(f,xh0,xh1)
        #undef GX_F
        #pragma unroll
        for(int kp=0;kp<4;kp++){
            G[r0*128+kp*32+lane]=a0[kp];
            if(has1) G[r1*128+kp*32+lane]=a1[kp];
        }
    }
}

// ------- LSTM recurrence (h-part only) --------------------------------------------
__global__ __launch_bounds__(256) void k_lstm(
    const float* __restrict__ Whh, const float* __restrict__ bih,
    const float* __restrict__ bhh, float* __restrict__ out){
    extern __shared__ float sWh[];
    int tid=threadIdx.x;
    load_paired(sWh,Whh,tid);
    __syncthreads();
    int wid=tid>>5, lane=tid&31;
    int M=g_M;
    unsigned long long bs[4];
    #pragma unroll
    for(int kp=0;kp<4;kp++){
        float blo=bih[lane+64*kp]+bhh[lane+64*kp];
        float bhi=bih[lane+64*kp+32]+bhh[lane+64*kp+32];
        PACK2(bs[kp],blo,bhi);
    }
    const unsigned long long* G=g_GX;
    for(int base=(blockIdx.x*8+wid)*4; base<M; base+=gridDim.x*32){
        int rid[4];
        #pragma unroll
        for(int nn=0;nn<4;nn++) rid[nn]=(base+nn<M)?g_mi[base+nn]:-1;
        float hl[4]={0,0,0,0}, hh[4]={0,0,0,0}, cl[4]={0,0,0,0}, ch[4]={0,0,0,0};
        for(int t=0;t<5;t++){
            unsigned long long acc[4][4];
            #pragma unroll
            for(int nn=0;nn<4;nn++){
                int sr=rid[nn]-4+t;
                bool ok=(rid[nn]>=0)&&(sr>=0);
                const unsigned long long* gp=G+(ok?sr:0)*128+lane;
                #pragma unroll
                for(int kp=0;kp<4;kp++) acc[nn][kp]=ok?gp[kp*32]:bs[kp];
            }
            if(t>0){
                #define LSTM_F(F,HS) { \
                    const unsigned long long* whP=(const unsigned long long*)&sWh[(F)*256]+lane; \
                    unsigned long long w0=whP[0],w1=whP[32],w2=whP[64],w3=whP[96]; \
                    _Pragma("unroll") \
                    for(int nn=0;nn<4;nn++){ \
                        float hv=__shfl_sync(0xffffffffu,HS[nn],(F)&31); \
                        unsigned long long hp; BCAST2(hp,hv); \
                        FMA2(acc[nn][0],hp,w0); FMA2(acc[nn][1],hp,w1); \
                        FMA2(acc[nn][2],hp,w2); FMA2(acc[nn][3],hp,w3); \
                    } }
                #pragma unroll 8
                for(int f=0;f<32;f++) LSTM_F(f,hl)
                #pragma unroll 8
                for(int f=32;f<64;f++) LSTM_F(f,hh)
                #undef LSTM_F
            }
            #pragma unroll
            for(int nn=0;nn<4;nn++){
                float il,ih,fl,fh,gl,gh,ol,oh;
                UNPACK2(il,ih,acc[nn][0]);
                UNPACK2(fl,fh,acc[nn][1]);
                UNPACK2(gl,gh,acc[nn][2]);
                UNPACK2(ol,oh,acc[nn][3]);
                cl[nn]=sigf(fl)*cl[nn]+sigf(il)*tanhf(gl); hl[nn]=sigf(ol)*tanhf(cl[nn]);
                ch[nn]=sigf(fh)*ch[nn]+sigf(ih)*tanhf(gh); hh[nn]=sigf(oh)*tanhf(ch[nn]);
            }
        }
        #pragma unroll
        for(int nn=0;nn<4;nn++){
            if(rid[nn]>=0){
                out[(base+nn)*64+lane]=hl[nn];
                out[(base+nn)*64+lane+32]=hh[nn];
            }
        }
    }
}

// ---------------- host ----------------
extern "C" void kernel_launch(void* const* d_in, const int* in_sizes, int n_in,
                              void* d_out, int out_size){
    const float* x=(const float*)d_in[0];
    const int* row=(const int*)d_in[1];
    const int* mask=(const int*)d_in[2];
    const float* W0=(const float*)d_in[3];  const float* b0=(const float*)d_in[4];
    const float* W1=(const float*)d_in[5];  const float* b1=(const float*)d_in[6];
    const float* pw=(const float*)d_in[7];
    const float* Wu=(const float*)d_in[8];  const float* bu=(const float*)d_in[9];
    const float* l0wih=(const float*)d_in[10]; const float* l0whh=(const float*)d_in[11];
    const float* l0bih=(const float*)d_in[12]; const float* l0bhh=(const float*)d_in[13];
    const float* fwih=(const float*)d_in[14];  const float* fwhh=(const float*)d_in[15];
    const float* fbih=(const float*)d_in[16];  const float* fbhh=(const float*)d_in[17];
    float* out=(float*)d_out;

    int n=in_sizes[0]/32;
    int e=in_sizes[1]/2;
    const int* col=row+e;
    int kk=(n+1)/2;
    int n16=n*16;
    int GN=(n+255)/256, GN16=(n16+255)/256, GE=(e+255)/256;
    int GW=(n*32+255)/256;       // warp-per-node grids

    static int smem_set=0;
    if(!smem_set){
        cudaFuncSetAttribute(k_lstm, cudaFuncAttributeMaxDynamicSharedMemorySize, WSMEM);
        cudaFuncSetAttribute(k_gx,   cudaFuncAttributeMaxDynamicSharedMemorySize, WSMEM);
        smem_set=1;
    }

    float *dX1,*dH,*dB1,*dB2,*dS,*dRES;
    cudaGetSymbolAddress((void**)&dX1,g_X1);
    cudaGetSymbolAddress((void**)&dH,g_H);
    cudaGetSymbolAddress((void**)&dB1,g_B1);
    cudaGetSymbolAddress((void**)&dB2,g_B2);
    cudaGetSymbolAddress((void**)&dS,g_S);
    cudaGetSymbolAddress((void**)&dRES,g_RES);
    float *dscore; cudaGetSymbolAddress((void**)&dscore,g_score);
    float *ddinvP; cudaGetSymbolAddress((void**)&ddinvP,g_dinvP);
    float *ddinv0; cudaGetSymbolAddress((void**)&ddinv0,g_dinv0);

    // init + CSR build
    k_init<<<(int)(HASHSZ/256),256>>>(pw,n);
    k_edge0<<<GE,256>>>(row,col,e,n);
    k_scan1<<<GN,256>>>(n);
    k_scan2<<<1,256>>>(GN);
    k_scan3<<<GN,256>>>(n,e);
    k_place<<<GE,256>>>(row,col,e);

    // conv0: Hs = dinv0.(x@W0); gather+fin+relu+score
    k_gemm<32><<<(n+15)/16,256>>>(x,W0,(const float*)0,dH,ddinv0,(float*)0,(const float*)0,n);
    k_gcng<1><<<GW,256>>>(dH,b0,pw,dX1,n);

    // topk select + mask compaction
    k_find1<<<1,256>>>(kk);
    k_hist2k<<<GN,256>>>(n);
    k_find2<<<1,256>>>(kk);
    k_markmik<<<GN,256>>>(mask,n);
    k_tiefix<<<1,1>>>();

    // diagonal of M^2 + pooled degrees
    k_ccK<<<GE,256>>>(row,col,e,n);
    k_sdeg<<<GN,256>>>(n);
    k_dinvPk<<<GN,256>>>(n);

    // conv1: h2 (H) + m = dinvP.h2 (B1); s gather; t+up fused
    k_gemm<64><<<(n+15)/16,256>>>(dX1,W1,dscore,dH,(const float*)0,dB1,ddinvP,n);
    k_sg<<<GW,256>>>(dB1,dS,n);
    k_tup<<<GW,256>>>(dS,dH,b1,dB2,n);

    // LSTM0
    k_gx<<<PGRID,256,WSMEM>>>(dX1,l0wih,l0bih,l0bhh,n);
    k_lstm<<<PGRID,256,WSMEM>>>(l0whh,l0bih,l0bhh,dB1);   // h0 -> B1
    k_xin4<<<GN16,256>>>(n16);                            // RES

    // final GCN -> out
    k_gemm<64><<<(n+15)/16,256>>>(dRES,Wu,(const float*)0,dH,ddinv0,(float*)0,(const float*)0,n);
    k_gcng<0><<<GW,256>>>(dH,bu,(const float*)0,out,n);

    // final LSTM
    k_gx<<<PGRID,256,WSMEM>>>(out,fwih,fbih,fbhh,n);
    k_lstm<<<PGRID,256,WSMEM>>>(fwhh,fbih,fbhh,dB1);
    k_scat_out4<<<GN16,256>>>(out,n16);
}

// round 8
// speedup vs baseline: 2.0275x; 1.1707x over previous
#include <cuda_runtime.h>
#include <math.h>

#define NMAX 50000
#define EMAX 400000
#define HASHSZ (1u<<21)
#define HASHMASK (HASHSZ-1u)
#define WSMEM (64*256*4)
#define PGRID 444

// ---------------- scratch ----------------
__device__ float g_X1 [NMAX*64];
__device__ float g_H  [NMAX*64];
__device__ float g_B1 [NMAX*64];
__device__ float g_B2 [NMAX*64];
__device__ float g_RES[NMAX*64];
__device__ float g_S  [NMAX*64];
__device__ unsigned long long g_GX[NMAX*128];
__device__ float g_dinv0[NMAX];
__device__ float g_dinvP[NMAX];
__device__ float g_score[NMAX];
__device__ float g_kept[NMAX];
__device__ float g_sdeg[NMAX];
__device__ unsigned g_key[NMAX];
__device__ int   g_icnt[NMAX];
__device__ int   g_cc[NMAX];
__device__ int   g_mi[NMAX];
__device__ int   g_pos[NMAX];
__device__ int   g_off[NMAX+1];
__device__ int   g_cur[NMAX];
__device__ int   g_eidx[EMAX];
__device__ int   g_bsum[256];
__device__ int   g_bscan[256];
__device__ int   g_hist[65536];
__device__ int   g_hist2[65536];
__device__ int   g_tie[4096];
__device__ int   g_M, g_tcnt, g_selB, g_before, g_needed;
__device__ unsigned g_T;
__device__ float g_pwnorm;
__device__ unsigned long long g_hk[HASHSZ];
__device__ int   g_hc[HASHSZ];

__device__ __forceinline__ float sigf(float x){ return 1.0f/(1.0f+expf(-x)); }

#define FMA2(A,B,C) asm("fma.rn.f32x2 %0,%1,%2,%0;":"+l"(A):"l"(B),"l"(C))
#define PACK2(D,LO,HI) asm("mov.b64 %0,{%1,%2};":"=l"(D):"f"(LO),"f"(HI))
#define BCAST2(D,V) asm("mov.b64 %0,{%1,%1};":"=l"(D):"f"(V))
#define UNPACK2(LO,HI,S) asm("mov.b64 {%0,%1},%2;":"=f"(LO),"=f"(HI):"l"(S))

// ------- fused init ---------------------------------------------------------------
__global__ void k_init(const float* __restrict__ pw, int n){
    int i=blockIdx.x*blockDim.x+threadIdx.x;
    if(i<(int)HASHSZ){ g_hk[i]=~0ull; g_hc[i]=0; }
    if(i<n){ g_icnt[i]=0; g_cc[i]=0; }
    if(i<65536){ g_hist[i]=0; g_hist2[i]=0; }
    if(i==0){ g_M=0; g_tcnt=0; }
    if(blockIdx.x==0&&threadIdx.x<32){
        int l=threadIdx.x;
        float v=pw[l]*pw[l]+pw[l+32]*pw[l+32];
        for(int o=16;o;o>>=1) v+=__shfl_down_sync(0xffffffffu,v,o);
        if(l==0) g_pwnorm=sqrtf(v);
    }
}

// ------- edge pass: in-degree + hash insert ---------------------------------------
__device__ __forceinline__ unsigned hmix(unsigned long long x){
    x^=x>>30; x*=0xbf58476d1ce4e5b9ull;
    x^=x>>27; x*=0x94d049bb133111ebull;
    x^=x>>31;
    return (unsigned)x&HASHMASK;
}
__global__ void k_edge0(const int* __restrict__ row, const int* __restrict__ col, int e, int n){
    int i=blockIdx.x*blockDim.x+threadIdx.x;
    if(i>=e) return;
    atomicAdd(&g_icnt[col[i]],1);
    unsigned long long key=(unsigned long long)row[i]*(unsigned)n+(unsigned)col[i];
    unsigned h=hmix(key);
    while(true){
        unsigned long long prev=atomicCAS(&g_hk[h],~0ull,key);
        if(prev==~0ull||prev==key){ atomicAdd(&g_hc[h],1); break; }
        h=(h+1)&HASHMASK;
    }
}

// ------- CSR build ----------------------------------------------------------------
__global__ void k_scan1(int n){
    __shared__ int s[256];
    int t=threadIdx.x, i=blockIdx.x*256+t;
    int v=(i<n)?g_icnt[i]:0;
    if(i<n) g_dinv0[i]=rsqrtf((float)v+2.0f);
    s[t]=v; __syncthreads();
    for(int o=128;o;o>>=1){ if(t<o) s[t]+=s[t+o]; __syncthreads(); }
    if(t==0) g_bsum[blockIdx.x]=s[0];
}
__global__ void k_scan2(int nb){
    __shared__ int s[256];
    int t=threadIdx.x;
    int v=(t<nb)?g_bsum[t]:0;
    s[t]=v; __syncthreads();
    for(int o=1;o<256;o<<=1){
        int u=(t>=o)?s[t-o]:0; __syncthreads();
        s[t]+=u; __syncthreads();
    }
    g_bscan[t]=s[t]-v;
}
__global__ void k_scan3(int n, int e){
    __shared__ int s[256];
    int t=threadIdx.x, i=blockIdx.x*256+t;
    int v=(i<n)?g_icnt[i]:0;
    s[t]=v; __syncthreads();
    for(int o=1;o<256;o<<=1){
        int u=(t>=o)?s[t-o]:0; __syncthreads();
        s[t]+=u; __syncthreads();
    }
    if(i<n){
        int off=g_bscan[blockIdx.x]+s[t]-v;
        g_off[i]=off; g_cur[i]=off;
        if(i==n-1) g_off[n]=e;
    }
}
__global__ void k_place(const int* __restrict__ row, const int* __restrict__ col, int e){
    int i=blockIdx.x*blockDim.x+threadIdx.x;
    if(i<e){
        int p=atomicAdd(&g_cur[col[i]],1);
        g_eidx[p]=row[i];
    }
}

// ------- dense GEMM ----------------------------------------------------------------
template<int K>
__global__ void k_gemm(const float* __restrict__ X, const float* __restrict__ W,
                       const float* __restrict__ rs, float* __restrict__ out,
                       const float* __restrict__ scale1,
                       float* __restrict__ out2, const float* __restrict__ scale2, int n){
    __shared__ float sW[K*64];
    __shared__ float sX[16*K];
    int tid=threadIdx.x;
    for(int i=tid;i<K*64;i+=256) sW[i]=W[i];
    int r0=blockIdx.x*16;
    for(int i=tid;i<16*K;i+=256){
        int rr=i/K, kk=i%K, row=r0+rr;
        float v=0.0f;
        if(row<n){ v=X[row*K+kk]; if(rs) v*=rs[row]; }
        sX[i]=v;
    }
    __syncthreads();
    int c=tid&63, rg=tid>>6;
    float a0=0,a1=0,a2=0,a3=0;
    #pragma unroll 8
    for(int kk=0;kk<K;kk++){
        float w=sW[kk*64+c];
        a0+=sX[(rg*4+0)*K+kk]*w;
        a1+=sX[(rg*4+1)*K+kk]*w;
        a2+=sX[(rg*4+2)*K+kk]*w;
        a3+=sX[(rg*4+3)*K+kk]*w;
    }
    int row=r0+rg*4;
    #pragma unroll
    for(int rr=0;rr<4;rr++){
        float a=(rr==0)?a0:(rr==1)?a1:(rr==2)?a2:a3;
        if(row+rr<n){
            out[(row+rr)*64+c]=scale1?scale1[row+rr]*a:a;
            if(out2) out2[(row+rr)*64+c]=scale2[row+rr]*a;
        }
    }
}

// ------- GCN gather (warp/node) ----------------------------------------------------
// MODE 1 (conv0): H unscaled; per-edge dinv0 scaling; relu + score + hist
// MODE 0 (final): H pre-scaled by dinv0; plain
template<int MODE>
__global__ void k_gcng(const float* __restrict__ Hs, const float* __restrict__ b,
                       const float* __restrict__ pw, float* __restrict__ out, int n){
    int node=(blockIdx.x*blockDim.x+threadIdx.x)>>5;
    int l=threadIdx.x&31;
    if(node>=n) return;
    float d=g_dinv0[node];
    float alo,ahi;
    int s0=g_off[node], s1=g_off[node+1];
    if(MODE==1){
        alo=2.0f*d*Hs[node*64+l]; ahi=2.0f*d*Hs[node*64+l+32];
        for(int j=s0;j<s1;j++){
            int r=g_eidx[j];
            float dr=g_dinv0[r];
            alo+=dr*Hs[r*64+l];
            ahi+=dr*Hs[r*64+l+32];
        }
    }else{
        alo=2.0f*Hs[node*64+l]; ahi=2.0f*Hs[node*64+l+32];
        for(int j=s0;j<s1;j++){
            int r=g_eidx[j];
            alo+=Hs[r*64+l];
            ahi+=Hs[r*64+l+32];
        }
    }
    float vlo=d*alo+b[l], vhi=d*ahi+b[l+32];
    if(MODE==1){
        vlo=fmaxf(vlo,0.0f); vhi=fmaxf(vhi,0.0f);
        out[node*64+l]=vlo; out[node*64+l+32]=vhi;
        float s=vlo*pw[l]+vhi*pw[l+32];
        for(int o=16;o;o>>=1) s+=__shfl_down_sync(0xffffffffu,s,o);
        if(l==0){
            float sc=tanhf(s/g_pwnorm);
            g_score[node]=sc;
            unsigned bb=__float_as_uint(sc);
            unsigned key=(bb&0x80000000u)?~bb:(bb|0x80000000u);
            g_key[node]=key;
            atomicAdd(&g_hist[key>>16],1);
        }
    }else{
        out[node*64+l]=vlo; out[node*64+l+32]=vhi;
    }
}
__global__ void k_sg(const float* __restrict__ m, float* __restrict__ s, int n){
    int node=(blockIdx.x*blockDim.x+threadIdx.x)>>5;
    int l=threadIdx.x&31;
    if(node>=n) return;
    float alo=0.0f, ahi=0.0f;
    int s0=g_off[node], s1=g_off[node+1];
    for(int j=s0;j<s1;j++){
        int r=g_eidx[j];
        alo+=m[r*64+l];
        ahi+=m[r*64+l+32];
    }
    s[node*64+l]=alo; s[node*64+l+32]=ahi;
}
__global__ void k_tup(const float* __restrict__ s, const float* __restrict__ h2,
                      const float* __restrict__ b1, float* __restrict__ up, int n){
    int node=(blockIdx.x*blockDim.x+threadIdx.x)>>5;
    int l=threadIdx.x&31;
    if(node>=n) return;
    float dp=g_dinvP[node];
    if(dp==0.0f){
        up[node*64+l]=0.0f; up[node*64+l+32]=0.0f;
        return;
    }
    float alo=0.0f, ahi=0.0f;
    int s0=g_off[node], s1=g_off[node+1];
    for(int j=s0;j<s1;j++){
        int r=g_eidx[j];
        alo+=s[r*64+l];
        ahi+=s[r*64+l+32];
    }
    float cf=(2.0f-(float)g_cc[node])*dp;
    float vlo=fmaxf(dp*(alo+2.0f*s[node*64+l]   +cf*h2[node*64+l])   +b1[l],   0.0f);
    float vhi=fmaxf(dp*(ahi+2.0f*s[node*64+l+32]+cf*h2[node*64+l+32])+b1[l+32],0.0f);
    up[node*64+l]=vlo; up[node*64+l+32]=vhi;
}

// ---------------- radix select ----------------
__global__ void k_find1(int kk){
    __shared__ int cs[256]; __shared__ int fine[256]; __shared__ int sel;
    int t=threadIdx.x, s=0;
    for(int b=0;b<256;b++) s+=g_hist[t*256+b];
    cs[t]=s; __syncthreads();
    if(t==0){
        int acc=0, c;
        for(c=255;c>0;c--){ if(acc+cs[c]>=kk) break; acc+=cs[c]; }
        sel=c; g_before=acc;
    }
    __syncthreads();
    int c=sel;
    fine[t]=g_hist[c*256+t];
    __syncthreads();
    if(t==0){
        int acc=g_before;
        for(int b=255;b>=0;b--){
            acc+=fine[b];
            if(acc>=kk){ g_selB=c*256+b; g_before=acc-fine[b]; return; }
        }
        g_selB=c*256;
    }
}
__global__ void k_hist2k(int n){
    int i=blockIdx.x*blockDim.x+threadIdx.x;
    if(i<n){ unsigned u=g_key[i]; if((int)(u>>16)==g_selB) atomicAdd(&g_hist2[u&0xFFFFu],1); }
}
__global__ void k_find2(int kk){
    __shared__ int cs[256]; __shared__ int fine[256]; __shared__ int sel;
    int t=threadIdx.x, s=0;
    for(int b=0;b<256;b++) s+=g_hist2[t*256+b];
    cs[t]=s; __syncthreads();
    int rem=kk-g_before;
    if(t==0){
        int acc=0, c;
        for(c=255;c>0;c--){ if(acc+cs[c]>=rem) break; acc+=cs[c]; }
        sel=c; g_needed=acc;
    }
    __syncthreads();
    int c=sel;
    fine[t]=g_hist2[c*256+t];
    __syncthreads();
    if(t==0){
        int acc=g_needed;
        for(int b=255;b>=0;b--){
            acc+=fine[b];
            if(acc>=rem){
                g_T=((unsigned)g_selB<<16)|(unsigned)(c*256+b);
                g_needed=rem-(acc-fine[b]);
                return;
            }
        }
        g_T=(unsigned)g_selB<<16; g_needed=0;
    }
}
__global__ void k_markmik(const int* __restrict__ mask, int n){
    int i=blockIdx.x*blockDim.x+threadIdx.x;
    if(i<n){
        unsigned u=g_key[i];
        g_kept[i]=(u>g_T)?1.0f:0.0f;
        if(u==g_T){ int p=atomicAdd(&g_tcnt,1); if(p<4096) g_tie[p]=i; }
        int p=-1;
        if(mask[i]!=0){ p=atomicAdd(&g_M,1); g_mi[p]=i; }
        g_pos[i]=p;
    }
}
__global__ void k_tiefix(){
    int need=g_needed, tc=g_tcnt; if(tc>4096) tc=4096;
    for(int s=0;s<need&&s<tc;s++){
        int mb=s;
        for(int j=s+1;j<tc;j++) if(g_tie[j]<g_tie[mb]) mb=j;
        int tmp=g_tie[s]; g_tie[s]=g_tie[mb]; g_tie[mb]=tmp;
        g_kept[g_tie[s]]=1.0f;
    }
}

// ---------------- hash lookup → diagonal of M^2 ----------------
__global__ void k_ccK(const int* __restrict__ row, const int* __restrict__ col, int e, int n){
    int i=blockIdx.x*blockDim.x+threadIdx.x;
    if(i>=e) return;
    unsigned long long key=(unsigned long long)col[i]*(unsigned)n+(unsigned)row[i];
    unsigned h=hmix(key);
    int cnt=0;
    while(true){
        unsigned long long k2=g_hk[h];
        if(k2==key){ cnt=g_hc[h]; break; }
        if(k2==~0ull) break;
        h=(h+1)&HASHMASK;
    }
    if(cnt) atomicAdd(&g_cc[row[i]],cnt);
}
__global__ void k_sdeg(int n){
    int i=blockIdx.x*blockDim.x+threadIdx.x;
    if(i>=n) return;
    float s=0.0f;
    for(int j=g_off[i];j<g_off[i+1];j++) s+=g_kept[g_eidx[j]];
    g_sdeg[i]=s;
}
__global__ void k_dinvPk(int n){
    int i=blockIdx.x*blockDim.x+threadIdx.x;
    if(i>=n) return;
    float td=0.0f;
    for(int j=g_off[i];j<g_off[i+1];j++) td+=g_sdeg[g_eidx[j]];
    float degP=td+2.0f*g_sdeg[i]+2.0f-(float)g_cc[i];
    g_dinvP[i]=(g_kept[i]>0.5f)?rsqrtf(degP):0.0f;
}
__global__ void k_xin4(int n16){
    int i=blockIdx.x*blockDim.x+threadIdx.x;
    if(i<n16){
        int r=i>>4, fq=i&15;
        int p=g_pos[r];
        float4 v=(p>=0)?((const float4*)g_B1)[p*16+fq]:((const float4*)g_X1)[i];
        float4 u=((const float4*)g_B2)[i];
        v.x+=u.x; v.y+=u.y; v.z+=u.z; v.w+=u.w;
        ((float4*)g_RES)[i]=v;
    }
}

// ------- paired-weight smem loader ------------------------------------------------
__device__ __forceinline__ void load_paired(float* sW, const float* __restrict__ W, int tid){
    for(int i=tid*4;i<256*64;i+=256*4){
        int g=i>>6, f0=i&63;
        int j=g>>5, lg=g&31, kp=j>>1, half=j&1;
        int dbase=kp*64+lg*2+half;
        float4 w=*(const float4*)&W[i];
        sW[dbase+(f0+0)*256]=w.x; sW[dbase+(f0+1)*256]=w.y;
        sW[dbase+(f0+2)*256]=w.z; sW[dbase+(f0+3)*256]=w.w;
    }
}

// ------- Gx precompute ------------------------------------------------------------
__global__ __launch_bounds__(256) void k_gx(const float* __restrict__ Xsrc,
    const float* __restrict__ Wih, const float* __restrict__ bih,
    const float* __restrict__ bhh, int n){
    extern __shared__ float sWi[];
    int tid=threadIdx.x;
    load_paired(sWi,Wih,tid);
    __syncthreads();
    int wid=tid>>5, lane=tid&31;
    unsigned long long bs[4];
    #pragma unroll
    for(int kp=0;kp<4;kp++){
        float blo=bih[lane+64*kp]+bhh[lane+64*kp];
        float bhi=bih[lane+64*kp+32]+bhh[lane+64*kp+32];
        PACK2(bs[kp],blo,bhi);
    }
    unsigned long long* G=g_GX;
    for(int r0=(blockIdx.x*8+wid)*2; r0<n; r0+=gridDim.x*16){
        int r1=r0+1; bool has1=r1<n;
        float xl0=Xsrc[r0*64+lane], xh0=Xsrc[r0*64+lane+32];
        float xl1=has1?Xsrc[r1*64+lane]:0.0f, xh1=has1?Xsrc[r1*64+lane+32]:0.0f;
        unsigned long long a0[4],a1[4];
        #pragma unroll
        for(int kp=0;kp<4;kp++){ a0[kp]=bs[kp]; a1[kp]=bs[kp]; }
        #define GX_F(F,X0,X1S) { \
            const unsigned long long* wp=(const unsigned long long*)&sWi[(F)*256]+lane; \
            unsigned long long w0=wp[0],w1=wp[32],w2=wp[64],w3=wp[96]; \
            float xv0=__shfl_sync(0xffffffffu,X0,(F)&31); \
            float xv1=__shfl_sync(0xffffffffu,X1S,(F)&31); \
            unsigned long long p0,p1; BCAST2(p0,xv0); BCAST2(p1,xv1); \
            FMA2(a0[0],p0,w0); FMA2(a0[1],p0,w1); FMA2(a0[2],p0,w2); FMA2(a0[3],p0,w3); \
            FMA2(a1[0],p1,w0); FMA2(a1[1],p1,w1); FMA2(a1[2],p1,w2); FMA2(a1[3],p1,w3); }
        #pragma unroll 8
        for(int f=0;f<32;f++) GX_F(f,xl0,xl1)
        #pragma unroll 8
        for(int f=32;f<64;f++) GX_F(f,xh0,xh1)
        #undef GX_F
        #pragma unroll
        for(int kp=0;kp<4;kp++){
            G[r0*128+kp*32+lane]=a0[kp];
            if(has1) G[r1*128+kp*32+lane]=a1[kp];
        }
    }
}

// ------- LSTM recurrence (h-part only). DIRECT=1 writes out[rid] rows -------------
template<int DIRECT>
__global__ __launch_bounds__(256) void k_lstm(
    const float* __restrict__ Whh, const float* __restrict__ bih,
    const float* __restrict__ bhh, float* __restrict__ out){
    extern __shared__ float sWh[];
    int tid=threadIdx.x;
    load_paired(sWh,Whh,tid);
    __syncthreads();
    int wid=tid>>5, lane=tid&31;
    int M=g_M;
    unsigned long long bs[4];
    #pragma unroll
    for(int kp=0;kp<4;kp++){
        float blo=bih[lane+64*kp]+bhh[lane+64*kp];
        float bhi=bih[lane+64*kp+32]+bhh[lane+64*kp+32];
        PACK2(bs[kp],blo,bhi);
    }
    const unsigned long long* G=g_GX;
    for(int base=(blockIdx.x*8+wid)*4; base<M; base+=gridDim.x*32){
        int rid[4];
        #pragma unroll
        for(int nn=0;nn<4;nn++) rid[nn]=(base+nn<M)?g_mi[base+nn]:-1;
        float hl[4]={0,0,0,0}, hh[4]={0,0,0,0}, cl[4]={0,0,0,0}, ch[4]={0,0,0,0};
        for(int t=0;t<5;t++){
            unsigned long long acc[4][4];
            #pragma unroll
            for(int nn=0;nn<4;nn++){
                int sr=rid[nn]-4+t;
                bool ok=(rid[nn]>=0)&&(sr>=0);
                const unsigned long long* gp=G+(ok?sr:0)*128+lane;
                #pragma unroll
                for(int kp=0;kp<4;kp++) acc[nn][kp]=ok?gp[kp*32]:bs[kp];
            }
            if(t>0){
                #define LSTM_F(F,HS) { \
                    const unsigned long long* whP=(const unsigned long long*)&sWh[(F)*256]+lane; \
                    unsigned long long w0=whP[0],w1=whP[32],w2=whP[64],w3=whP[96]; \
                    _Pragma("unroll") \
                    for(int nn=0;nn<4;nn++){ \
                        float hv=__shfl_sync(0xffffffffu,HS[nn],(F)&31); \
                        unsigned long long hp; BCAST2(hp,hv); \
                        FMA2(acc[nn][0],hp,w0); FMA2(acc[nn][1],hp,w1); \
                        FMA2(acc[nn][2],hp,w2); FMA2(acc[nn][3],hp,w3); \
                    } }
                #pragma unroll 8
                for(int f=0;f<32;f++) LSTM_F(f,hl)
                #pragma unroll 8
                for(int f=32;f<64;f++) LSTM_F(f,hh)
                #undef LSTM_F
            }
            #pragma unroll
            for(int nn=0;nn<4;nn++){
                float il,ih,fl,fh,gl,gh,ol,oh;
                UNPACK2(il,ih,acc[nn][0]);
                UNPACK2(fl,fh,acc[nn][1]);
                UNPACK2(gl,gh,acc[nn][2]);
                UNPACK2(ol,oh,acc[nn][3]);
                cl[nn]=sigf(fl)*cl[nn]+sigf(il)*tanhf(gl); hl[nn]=sigf(ol)*tanhf(cl[nn]);
                ch[nn]=sigf(fh)*ch[nn]+sigf(ih)*tanhf(gh); hh[nn]=sigf(oh)*tanhf(ch[nn]);
            }
        }
        #pragma unroll
        for(int nn=0;nn<4;nn++){
            if(rid[nn]>=0){
                int orow=DIRECT?rid[nn]:(base+nn);
                out[orow*64+lane]=hl[nn];
                out[orow*64+lane+32]=hh[nn];
            }
        }
    }
}

// ---------------- host ----------------
extern "C" void kernel_launch(void* const* d_in, const int* in_sizes, int n_in,
                              void* d_out, int out_size){
    const float* x=(const float*)d_in[0];
    const int* row=(const int*)d_in[1];
    const int* mask=(const int*)d_in[2];
    const float* W0=(const float*)d_in[3];  const float* b0=(const float*)d_in[4];
    const float* W1=(const float*)d_in[5];  const float* b1=(const float*)d_in[6];
    const float* pw=(const float*)d_in[7];
    const float* Wu=(const float*)d_in[8];  const float* bu=(const float*)d_in[9];
    const float* l0wih=(const float*)d_in[10]; const float* l0whh=(const float*)d_in[11];
    const float* l0bih=(const float*)d_in[12]; const float* l0bhh=(const float*)d_in[13];
    const float* fwih=(const float*)d_in[14];  const float* fwhh=(const float*)d_in[15];
    const float* fbih=(const float*)d_in[16];  const float* fbhh=(const float*)d_in[17];
    float* out=(float*)d_out;

    int n=in_sizes[0]/32;
    int e=in_sizes[1]/2;
    const int* col=row+e;
    int kk=(n+1)/2;
    int n16=n*16;
    int GN=(n+255)/256, GN16=(n16+255)/256, GE=(e+255)/256;
    int GW=(n*32+255)/256;

    static cudaStream_t sA=0,sB=0,sC=0;
    static cudaEvent_t evRoot=0,evG=0,evCSR=0,evCC=0,evX1=0,evMik=0,evL0=0;
    if(!sA){
        cudaFuncSetAttribute(k_lstm<0>, cudaFuncAttributeMaxDynamicSharedMemorySize, WSMEM);
        cudaFuncSetAttribute(k_lstm<1>, cudaFuncAttributeMaxDynamicSharedMemorySize, WSMEM);
        cudaFuncSetAttribute(k_gx,      cudaFuncAttributeMaxDynamicSharedMemorySize, WSMEM);
        cudaStreamCreateWithFlags(&sA,cudaStreamNonBlocking);
        cudaStreamCreateWithFlags(&sB,cudaStreamNonBlocking);
        cudaStreamCreateWithFlags(&sC,cudaStreamNonBlocking);
        cudaEventCreateWithFlags(&evRoot,cudaEventDisableTiming);
        cudaEventCreateWithFlags(&evG,cudaEventDisableTiming);
        cudaEventCreateWithFlags(&evCSR,cudaEventDisableTiming);
        cudaEventCreateWithFlags(&evCC,cudaEventDisableTiming);
        cudaEventCreateWithFlags(&evX1,cudaEventDisableTiming);
        cudaEventCreateWithFlags(&evMik,cudaEventDisableTiming);
        cudaEventCreateWithFlags(&evL0,cudaEventDisableTiming);
    }

    float *dX1,*dH,*dB1,*dB2,*dS,*dRES;
    cudaGetSymbolAddress((void**)&dX1,g_X1);
    cudaGetSymbolAddress((void**)&dH,g_H);
    cudaGetSymbolAddress((void**)&dB1,g_B1);
    cudaGetSymbolAddress((void**)&dB2,g_B2);
    cudaGetSymbolAddress((void**)&dS,g_S);
    cudaGetSymbolAddress((void**)&dRES,g_RES);
    float *dscore; cudaGetSymbolAddress((void**)&dscore,g_score);
    float *ddinvP; cudaGetSymbolAddress((void**)&ddinvP,g_dinvP);
    float *ddinv0; cudaGetSymbolAddress((void**)&ddinv0,g_dinv0);

    // fork: conv0 GEMM (independent) on sA
    cudaEventRecord(evRoot,0);
    cudaStreamWaitEvent(sA,evRoot,0);
    k_gemm<32><<<(n+15)/16,256,0,sA>>>(x,W0,(const float*)0,dH,(const float*)0,(float*)0,(const float*)0,n);
    cudaEventRecord(evG,sA);

    // main: init + edges + CSR
    k_init<<<(int)(HASHSZ/256),256>>>(pw,n);
    k_edge0<<<GE,256>>>(row,col,e,n);
    k_scan1<<<GN,256>>>(n);
    k_scan2<<<1,256>>>(GN);
    k_scan3<<<GN,256>>>(n,e);
    k_place<<<GE,256>>>(row,col,e);
    cudaEventRecord(evCSR,0);

    // ccK on sC (needs only hash, done in edge0; CSR event covers it)
    cudaStreamWaitEvent(sC,evCSR,0);
    k_ccK<<<GE,256,0,sC>>>(row,col,e,n);
    cudaEventRecord(evCC,sC);

    // conv0 gather (needs H from sA + CSR)
    cudaStreamWaitEvent(0,evG,0);
    k_gcng<1><<<GW,256>>>(dH,b0,pw,dX1,n);
    cudaEventRecord(evX1,0);

    // LSTM0 Gx on sB (needs only X1)
    cudaStreamWaitEvent(sB,evX1,0);
    k_gx<<<PGRID,256,WSMEM,sB>>>(dX1,l0wih,l0bih,l0bhh,n);

    // selection on main
    k_find1<<<1,256>>>(kk);
    k_hist2k<<<GN,256>>>(n);
    k_find2<<<1,256>>>(kk);
    k_markmik<<<GN,256>>>(mask,n);
    cudaEventRecord(evMik,0);
    k_tiefix<<<1,1>>>();

    // LSTM0 recurrence on sB (needs g_mi/g_M)
    cudaStreamWaitEvent(sB,evMik,0);
    k_lstm<0><<<PGRID,256,WSMEM,sB>>>(l0whh,l0bih,l0bhh,dB1);   // h0 -> B1 compact
    cudaEventRecord(evL0,sB);

    // branch A on main: pooled degrees + conv1
    k_sdeg<<<GN,256>>>(n);
    cudaStreamWaitEvent(0,evCC,0);
    k_dinvPk<<<GN,256>>>(n);
    k_gemm<64><<<(n+15)/16,256>>>(dX1,W1,dscore,dH,(const float*)0,dB2,ddinvP,n); // h2->H, m->B2
    k_sg<<<GW,256>>>(dB2,dS,n);
    k_tup<<<GW,256>>>(dS,dH,b1,dB2,n);                          // up -> B2

    // join LSTM0, build RES, final conv, final LSTM
    cudaStreamWaitEvent(0,evL0,0);
    k_xin4<<<GN16,256>>>(n16);
    k_gemm<64><<<(n+15)/16,256>>>(dRES,Wu,(const float*)0,dH,ddinv0,(float*)0,(const float*)0,n);
    k_gcng<0><<<GW,256>>>(dH,bu,(const float*)0,out,n);
    k_gx<<<PGRID,256,WSMEM>>>(out,fwih,fbih,fbhh,n);
    k_lstm<1><<<PGRID,256,WSMEM>>>(fwhh,fbih,fbhh,out);
}